// round 1
// baseline (speedup 1.0000x reference)
#include <cuda_runtime.h>
#include <math.h>

// Problem constants
#define BQ 65536
#define DQ 784
#define HQ 392
#define LQ 32
#define NT4 13                 // ceil(784/64) N-tiles in gemm4
#define NB1 ((BQ) / 64)        // 1024 row blocks
#define NRED 256               // row-reduction blocks (65536 / 256)

// Scratch (static device globals; no allocation in kernel_launch)
__device__ float g_h[BQ * HQ];          // encoder hidden   [B,H]
__device__ float g_z[BQ * LQ];          // latent z         [B,L]
__device__ float g_hd[BQ * HQ];         // decoder hidden   [B,H]
__device__ float g_quadpart[BQ * NT4];  // per (row, n-tile) quad partials
__device__ float g_ldpart[BQ * NT4];    // per (row, n-tile) logdet partials
__device__ float g_klpart[NB1];         // per gemm2-block KL partials
__device__ float g_lppart[NRED];        // per reduce-block log_prob partials

// ---------------------------------------------------------------------------
// GEMM1: g_h = relu(x @ W_e1^T + b_e1)    M=B, K=784, N=392
// Tiled 64x64, BK=16, 256 thr, 4x4 microtile.
// ---------------------------------------------------------------------------
__global__ __launch_bounds__(256) void k_gemm1(
    const float* __restrict__ A, const float* __restrict__ W,
    const float* __restrict__ bias) {
  const int K = DQ, N = HQ;
  __shared__ float As[16][64];
  __shared__ float Ws[16][64];
  const int rb = blockIdx.x * 64;
  const int nb = blockIdx.y * 64;
  const int tid = threadIdx.x;
  const int tx = tid & 15, ty = tid >> 4;
  const int lm = tid >> 2;          // 0..63
  const int kq = (tid & 3) * 4;     // 0,4,8,12
  float acc[4][4] = {};
  for (int k0 = 0; k0 < K; k0 += 16) {
#pragma unroll
    for (int i = 0; i < 4; i++) {
      int k = k0 + kq + i;
      As[kq + i][lm] = (k < K) ? A[(size_t)(rb + lm) * K + k] : 0.f;
      float wv = 0.f;
      int n = nb + lm;
      if (n < N && k < K) wv = W[(size_t)n * K + k];
      Ws[kq + i][lm] = wv;
    }
    __syncthreads();
#pragma unroll
    for (int kk = 0; kk < 16; kk++) {
      float a[4], w[4];
#pragma unroll
      for (int i = 0; i < 4; i++) a[i] = As[kk][ty * 4 + i];
#pragma unroll
      for (int j = 0; j < 4; j++) w[j] = Ws[kk][tx * 4 + j];
#pragma unroll
      for (int i = 0; i < 4; i++)
#pragma unroll
        for (int j = 0; j < 4; j++) acc[i][j] += a[i] * w[j];
    }
    __syncthreads();
  }
#pragma unroll
  for (int i = 0; i < 4; i++) {
    int r = rb + ty * 4 + i;
#pragma unroll
    for (int j = 0; j < 4; j++) {
      int n = nb + tx * 4 + j;
      if (n < N) g_h[(size_t)r * N + n] = fmaxf(acc[i][j] + bias[n], 0.f);
    }
  }
}

// ---------------------------------------------------------------------------
// GEMM2: mu_z = relu(h @ W_emu^T + b), lv_z = relu(h @ W_elv^T + b)
// Combined N=64 (cols 0..31 mu, 32..63 lv). Fused: z = mu + eps_z*exp(.5 lv),
// per-block KL partial. K=392.
// ---------------------------------------------------------------------------
__global__ __launch_bounds__(256) void k_gemm2(
    const float* __restrict__ Wmu, const float* __restrict__ bmu,
    const float* __restrict__ Wlv, const float* __restrict__ blv,
    const float* __restrict__ eps_z) {
  const int K = HQ;
  __shared__ float As[16][64];
  __shared__ float Ws[16][64];
  __shared__ float s_out[64][65];
  const int rb = blockIdx.x * 64;
  const int tid = threadIdx.x;
  const int tx = tid & 15, ty = tid >> 4;
  const int lm = tid >> 2;
  const int kq = (tid & 3) * 4;
  float acc[4][4] = {};
  for (int k0 = 0; k0 < K; k0 += 16) {
#pragma unroll
    for (int i = 0; i < 4; i++) {
      int k = k0 + kq + i;
      As[kq + i][lm] = (k < K) ? g_h[(size_t)(rb + lm) * K + k] : 0.f;
      float wv = 0.f;
      if (k < K) {
        wv = (lm < 32) ? Wmu[(size_t)lm * K + k]
                       : Wlv[(size_t)(lm - 32) * K + k];
      }
      Ws[kq + i][lm] = wv;
    }
    __syncthreads();
#pragma unroll
    for (int kk = 0; kk < 16; kk++) {
      float a[4], w[4];
#pragma unroll
      for (int i = 0; i < 4; i++) a[i] = As[kk][ty * 4 + i];
#pragma unroll
      for (int j = 0; j < 4; j++) w[j] = Ws[kk][tx * 4 + j];
#pragma unroll
      for (int i = 0; i < 4; i++)
#pragma unroll
        for (int j = 0; j < 4; j++) acc[i][j] += a[i] * w[j];
    }
    __syncthreads();
  }
  // stage relu(acc + bias)
#pragma unroll
  for (int i = 0; i < 4; i++)
#pragma unroll
    for (int j = 0; j < 4; j++) {
      int c = tx * 4 + j;
      float b = (c < 32) ? bmu[c] : blv[c - 32];
      s_out[ty * 4 + i][c] = fmaxf(acc[i][j] + b, 0.f);
    }
  __syncthreads();
  float kl = 0.f;
  for (int idx = tid; idx < 64 * 32; idx += 256) {
    int r = idx >> 5, c = idx & 31;
    float mu = s_out[r][c];
    float lv = s_out[r][c + 32];
    int row = rb + r;
    float elv = expf(lv);
    g_z[(size_t)row * LQ + c] =
        mu + eps_z[(size_t)row * LQ + c] * expf(0.5f * lv);
    kl += 0.5f * (mu * mu + elv - logf(1e-8f + elv) - 1.f);
  }
  __shared__ float sred[256];
  sred[tid] = kl;
  __syncthreads();
  for (int s = 128; s > 0; s >>= 1) {
    if (tid < s) sred[tid] += sred[tid + s];
    __syncthreads();
  }
  if (tid == 0) g_klpart[blockIdx.x] = sred[0];
}

// ---------------------------------------------------------------------------
// GEMM3: g_hd = relu(z @ W_d1^T + b_d1)   M=B, K=32, N=392
// ---------------------------------------------------------------------------
__global__ __launch_bounds__(256) void k_gemm3(
    const float* __restrict__ W, const float* __restrict__ bias) {
  const int K = LQ, N = HQ;
  __shared__ float As[16][64];
  __shared__ float Ws[16][64];
  const int rb = blockIdx.x * 64;
  const int nb = blockIdx.y * 64;
  const int tid = threadIdx.x;
  const int tx = tid & 15, ty = tid >> 4;
  const int lm = tid >> 2;
  const int kq = (tid & 3) * 4;
  float acc[4][4] = {};
  for (int k0 = 0; k0 < K; k0 += 16) {
#pragma unroll
    for (int i = 0; i < 4; i++) {
      int k = k0 + kq + i;
      As[kq + i][lm] = g_z[(size_t)(rb + lm) * K + k];
      float wv = 0.f;
      int n = nb + lm;
      if (n < N) wv = W[(size_t)n * K + k];
      Ws[kq + i][lm] = wv;
    }
    __syncthreads();
#pragma unroll
    for (int kk = 0; kk < 16; kk++) {
      float a[4], w[4];
#pragma unroll
      for (int i = 0; i < 4; i++) a[i] = As[kk][ty * 4 + i];
#pragma unroll
      for (int j = 0; j < 4; j++) w[j] = Ws[kk][tx * 4 + j];
#pragma unroll
      for (int i = 0; i < 4; i++)
#pragma unroll
        for (int j = 0; j < 4; j++) acc[i][j] += a[i] * w[j];
    }
    __syncthreads();
  }
#pragma unroll
  for (int i = 0; i < 4; i++) {
    int r = rb + ty * 4 + i;
#pragma unroll
    for (int j = 0; j < 4; j++) {
      int n = nb + tx * 4 + j;
      if (n < N) g_hd[(size_t)r * N + n] = fmaxf(acc[i][j] + bias[n], 0.f);
    }
  }
}

// ---------------------------------------------------------------------------
// GEMM4: dual GEMM mu_y / lv_y from g_hd (K=392, N=784), fused epilogue:
//   image = sigmoid(mu + eps_y*exp(.5 lv)) -> out
//   per (row, n-tile) partials of quad = sum (x-mu)^2/exp(.5 lv), logdet
// ---------------------------------------------------------------------------
__global__ __launch_bounds__(256) void k_gemm4(
    const float* __restrict__ Wmu, const float* __restrict__ bmu,
    const float* __restrict__ Wlv, const float* __restrict__ blv,
    const float* __restrict__ x, const float* __restrict__ eps_y,
    float* __restrict__ out) {
  const int K = HQ, N = DQ;
  __shared__ float As[16][64];
  __shared__ float Wm[16][64];
  __shared__ float Wl[16][64];
  __shared__ float sq[64][17];
  __shared__ float sl[64][17];
  const int rb = blockIdx.x * 64;
  const int nb = blockIdx.y * 64;
  const int tid = threadIdx.x;
  const int tx = tid & 15, ty = tid >> 4;
  const int lm = tid >> 2;
  const int kq = (tid & 3) * 4;
  float accMu[4][4] = {};
  float accLv[4][4] = {};
  for (int k0 = 0; k0 < K; k0 += 16) {
#pragma unroll
    for (int i = 0; i < 4; i++) {
      int k = k0 + kq + i;
      As[kq + i][lm] = (k < K) ? g_hd[(size_t)(rb + lm) * K + k] : 0.f;
      float wm = 0.f, wl = 0.f;
      int n = nb + lm;
      if (n < N && k < K) {
        wm = Wmu[(size_t)n * K + k];
        wl = Wlv[(size_t)n * K + k];
      }
      Wm[kq + i][lm] = wm;
      Wl[kq + i][lm] = wl;
    }
    __syncthreads();
#pragma unroll
    for (int kk = 0; kk < 16; kk++) {
      float a[4], wm[4], wl[4];
#pragma unroll
      for (int i = 0; i < 4; i++) a[i] = As[kk][ty * 4 + i];
#pragma unroll
      for (int j = 0; j < 4; j++) {
        wm[j] = Wm[kk][tx * 4 + j];
        wl[j] = Wl[kk][tx * 4 + j];
      }
#pragma unroll
      for (int i = 0; i < 4; i++)
#pragma unroll
        for (int j = 0; j < 4; j++) {
          accMu[i][j] += a[i] * wm[j];
          accLv[i][j] += a[i] * wl[j];
        }
    }
    __syncthreads();
  }
  // epilogue
#pragma unroll
  for (int i = 0; i < 4; i++) {
    int r = rb + ty * 4 + i;
    float q = 0.f, l = 0.f;
#pragma unroll
    for (int j = 0; j < 4; j++) {
      int n = nb + tx * 4 + j;
      if (n < N) {
        float mu = fmaxf(accMu[i][j] + bmu[n], 0.f);
        float lv = fmaxf(accLv[i][j] + blv[n], 0.f);
        float s = expf(0.5f * lv);
        size_t off = (size_t)r * DQ + n;
        float t = mu + eps_y[off] * s;
        out[off] = 1.f / (1.f + expf(-t));
        float d = x[off] - mu;
        q += d * d / s;
        l += 0.5f * lv;
      }
    }
    sq[ty * 4 + i][tx] = q;
    sl[ty * 4 + i][tx] = l;
  }
  __syncthreads();
  if (tid < 64) {
    float q = 0.f, l = 0.f;
#pragma unroll
    for (int t = 0; t < 16; t++) {
      q += sq[tid][t];
      l += sl[tid][t];
    }
    g_quadpart[(size_t)(rb + tid) * NT4 + blockIdx.y] = q;
    g_ldpart[(size_t)(rb + tid) * NT4 + blockIdx.y] = l;
  }
}

// ---------------------------------------------------------------------------
// Row reduction: per-row log_prob, then per-block partial sum.
// ---------------------------------------------------------------------------
__global__ __launch_bounds__(256) void k_reduce_rows() {
  int row = blockIdx.x * 256 + threadIdx.x;
  float q = 0.f, l = 0.f;
#pragma unroll
  for (int t = 0; t < NT4; t++) {
    q += g_quadpart[(size_t)row * NT4 + t];
    l += g_ldpart[(size_t)row * NT4 + t];
  }
  float lp = -0.5f * (784.f * 1.8378770664093453f + l + q);
  __shared__ float sred[256];
  sred[threadIdx.x] = lp;
  __syncthreads();
  for (int s = 128; s > 0; s >>= 1) {
    if (threadIdx.x < s) sred[threadIdx.x] += sred[threadIdx.x + s];
    __syncthreads();
  }
  if (threadIdx.x == 0) g_lppart[blockIdx.x] = sred[0];
}

// ---------------------------------------------------------------------------
// Final scalar: loss = -mean(log_prob) + KL_total -> out[B*D]
// ---------------------------------------------------------------------------
__global__ __launch_bounds__(256) void k_final(float* __restrict__ out,
                                               int out_size) {
  __shared__ double sd[256];
  int tid = threadIdx.x;
  sd[tid] = (double)g_lppart[tid];
  __syncthreads();
  for (int s = 128; s > 0; s >>= 1) {
    if (tid < s) sd[tid] += sd[tid + s];
    __syncthreads();
  }
  double lp_sum = sd[0];
  __syncthreads();
  double kl = 0.0;
  for (int i = tid; i < NB1; i += 256) kl += (double)g_klpart[i];
  sd[tid] = kl;
  __syncthreads();
  for (int s = 128; s > 0; s >>= 1) {
    if (tid < s) sd[tid] += sd[tid + s];
    __syncthreads();
  }
  if (tid == 0) {
    long long nimg = (long long)BQ * DQ;
    if ((long long)out_size > nimg) {
      out[(size_t)nimg] = (float)(-(lp_sum) / (double)BQ + sd[0]);
    }
  }
}

// ---------------------------------------------------------------------------
extern "C" void kernel_launch(void* const* d_in, const int* in_sizes, int n_in,
                              void* d_out, int out_size) {
  const float* x     = (const float*)d_in[0];
  const float* eps_z = (const float*)d_in[1];
  const float* eps_y = (const float*)d_in[2];
  const float* W_e1  = (const float*)d_in[3];
  const float* b_e1  = (const float*)d_in[4];
  const float* W_emu = (const float*)d_in[5];
  const float* b_emu = (const float*)d_in[6];
  const float* W_elv = (const float*)d_in[7];
  const float* b_elv = (const float*)d_in[8];
  const float* W_d1  = (const float*)d_in[9];
  const float* b_d1  = (const float*)d_in[10];
  const float* W_dmu = (const float*)d_in[11];
  const float* b_dmu = (const float*)d_in[12];
  const float* W_dlv = (const float*)d_in[13];
  const float* b_dlv = (const float*)d_in[14];
  float* out = (float*)d_out;

  dim3 blk(256);
  k_gemm1<<<dim3(NB1, (HQ + 63) / 64), blk>>>(x, W_e1, b_e1);
  k_gemm2<<<dim3(NB1, 1), blk>>>(W_emu, b_emu, W_elv, b_elv, eps_z);
  k_gemm3<<<dim3(NB1, (HQ + 63) / 64), blk>>>(W_d1, b_d1);
  k_gemm4<<<dim3(NB1, NT4), blk>>>(W_dmu, b_dmu, W_dlv, b_dlv, x, eps_y, out);
  k_reduce_rows<<<NRED, blk>>>();
  k_final<<<1, blk>>>(out, out_size);
}

// round 2
// speedup vs baseline: 1.2630x; 1.2630x over previous
#include <cuda_runtime.h>
#include <math.h>

// Problem constants
#define BQ 65536
#define DQ 784
#define HQ 392
#define LQ 32
#define NT4 25                 // ceil(784/32) N-tiles in gemm4
#define NB1 ((BQ) / 64)        // 1024 row blocks (gemm2/3)
#define NRED 256               // row-reduction blocks (65536 / 256)

typedef unsigned long long ull;

// Scratch (static device globals; no allocation in kernel_launch)
__device__ float g_h[BQ * HQ];          // encoder hidden   [B,H]
__device__ float g_z[BQ * LQ];          // latent z         [B,L]
__device__ float g_hd[BQ * HQ];         // decoder hidden   [B,H]
__device__ float g_quadpart[(size_t)BQ * NT4];  // per (row, n-tile) quad partials
__device__ float g_ldpart[(size_t)BQ * NT4];    // per (row, n-tile) logdet partials
__device__ float g_klpart[NB1];         // per gemm2-block KL partials
__device__ float g_lppart[NRED];        // per reduce-block log_prob partials

// packed fp32x2 FMA (FFMA2) and pack helpers
__device__ __forceinline__ ull ffma2(ull a, ull b, ull c) {
  ull d;
  asm("fma.rn.f32x2 %0, %1, %2, %3;" : "=l"(d) : "l"(a), "l"(b), "l"(c));
  return d;
}
__device__ __forceinline__ ull dup2(float a) {
  ull r;
  asm("mov.b64 %0, {%1, %1};" : "=l"(r) : "f"(a));
  return r;
}
__device__ __forceinline__ float2 unpack2(ull v) {
  float2 f;
  asm("mov.b64 {%0, %1}, %2;" : "=f"(f.x), "=f"(f.y) : "l"(v));
  return f;
}

// ---------------------------------------------------------------------------
// GEMM1: g_h = relu(x @ W_e1^T + b_e1)    M=B, K=784, N=392
// Tile 256x64, BK=16, 256 thr, 8x8 microtile via FFMA2 (8x4 packed pairs).
// ---------------------------------------------------------------------------
__global__ __launch_bounds__(256, 2) void k_gemm1(
    const float* __restrict__ A, const float* __restrict__ W,
    const float* __restrict__ bias) {
  __shared__ __align__(16) float As[16][256];
  __shared__ __align__(16) float Ws[16][64];
  const int tid = threadIdx.x;
  const int rb = blockIdx.x * 256;
  const int nb = blockIdx.y * 64;
  const int tx = tid & 7, ty = tid >> 3;

  ull acc[8][4] = {};
  const float4* Arow = (const float4*)(A + (size_t)(rb + tid) * DQ);
  const int wn = tid >> 2;            // 0..63
  const int wkc = (tid & 3) * 4;      // 0,4,8,12
  const bool wvalid = (nb + wn) < HQ;
  const float4* Wrow =
      wvalid ? (const float4*)(W + (size_t)(nb + wn) * DQ) : nullptr;

  for (int k0 = 0; k0 < DQ; k0 += 16) {
    // stage A (transpose to As[k][row])
#pragma unroll
    for (int c = 0; c < 4; c++) {
      float4 v = Arow[(k0 >> 2) + c];
      As[c * 4 + 0][tid] = v.x;
      As[c * 4 + 1][tid] = v.y;
      As[c * 4 + 2][tid] = v.z;
      As[c * 4 + 3][tid] = v.w;
    }
    // stage W
    {
      float4 v = make_float4(0.f, 0.f, 0.f, 0.f);
      if (wvalid) v = Wrow[(k0 + wkc) >> 2];
      Ws[wkc + 0][wn] = v.x;
      Ws[wkc + 1][wn] = v.y;
      Ws[wkc + 2][wn] = v.z;
      Ws[wkc + 3][wn] = v.w;
    }
    __syncthreads();
#pragma unroll
    for (int kk = 0; kk < 16; kk++) {
      float4 a0 = *(const float4*)&As[kk][ty * 8];
      float4 a1 = *(const float4*)&As[kk][ty * 8 + 4];
      ull ad[8];
      ad[0] = dup2(a0.x); ad[1] = dup2(a0.y);
      ad[2] = dup2(a0.z); ad[3] = dup2(a0.w);
      ad[4] = dup2(a1.x); ad[5] = dup2(a1.y);
      ad[6] = dup2(a1.z); ad[7] = dup2(a1.w);
      ull w[4];
#pragma unroll
      for (int j = 0; j < 4; j++) w[j] = *(const ull*)&Ws[kk][tx * 8 + 2 * j];
#pragma unroll
      for (int i = 0; i < 8; i++)
#pragma unroll
        for (int j = 0; j < 4; j++) acc[i][j] = ffma2(ad[i], w[j], acc[i][j]);
    }
    __syncthreads();
  }
  // epilogue
#pragma unroll
  for (int i = 0; i < 8; i++) {
    size_t row = rb + ty * 8 + i;
#pragma unroll
    for (int j = 0; j < 4; j++) {
      int n = nb + tx * 8 + 2 * j;
      if (n < HQ) {
        float2 f = unpack2(acc[i][j]);
        f.x = fmaxf(f.x + bias[n], 0.f);
        f.y = fmaxf(f.y + bias[n + 1], 0.f);
        *(float2*)&g_h[row * HQ + n] = f;
      }
    }
  }
}

// ---------------------------------------------------------------------------
// GEMM2: mu_z = relu(h @ W_emu^T + b), lv_z = relu(h @ W_elv^T + b)
// Combined N=64 (cols 0..31 mu, 32..63 lv). Fused: z = mu + eps_z*exp(.5 lv),
// per-block KL partial. K=392.
// ---------------------------------------------------------------------------
__global__ __launch_bounds__(256) void k_gemm2(
    const float* __restrict__ Wmu, const float* __restrict__ bmu,
    const float* __restrict__ Wlv, const float* __restrict__ blv,
    const float* __restrict__ eps_z) {
  const int K = HQ;
  __shared__ float As[16][64];
  __shared__ float Ws[16][64];
  __shared__ float s_out[64][65];
  const int rb = blockIdx.x * 64;
  const int tid = threadIdx.x;
  const int tx = tid & 15, ty = tid >> 4;
  const int lm = tid >> 2;
  const int kq = (tid & 3) * 4;
  float acc[4][4] = {};
  for (int k0 = 0; k0 < K; k0 += 16) {
#pragma unroll
    for (int i = 0; i < 4; i++) {
      int k = k0 + kq + i;
      As[kq + i][lm] = (k < K) ? g_h[(size_t)(rb + lm) * K + k] : 0.f;
      float wv = 0.f;
      if (k < K) {
        wv = (lm < 32) ? Wmu[(size_t)lm * K + k]
                       : Wlv[(size_t)(lm - 32) * K + k];
      }
      Ws[kq + i][lm] = wv;
    }
    __syncthreads();
#pragma unroll
    for (int kk = 0; kk < 16; kk++) {
      float a[4], w[4];
#pragma unroll
      for (int i = 0; i < 4; i++) a[i] = As[kk][ty * 4 + i];
#pragma unroll
      for (int j = 0; j < 4; j++) w[j] = Ws[kk][tx * 4 + j];
#pragma unroll
      for (int i = 0; i < 4; i++)
#pragma unroll
        for (int j = 0; j < 4; j++) acc[i][j] += a[i] * w[j];
    }
    __syncthreads();
  }
#pragma unroll
  for (int i = 0; i < 4; i++)
#pragma unroll
    for (int j = 0; j < 4; j++) {
      int c = tx * 4 + j;
      float b = (c < 32) ? bmu[c] : blv[c - 32];
      s_out[ty * 4 + i][c] = fmaxf(acc[i][j] + b, 0.f);
    }
  __syncthreads();
  float kl = 0.f;
  for (int idx = tid; idx < 64 * 32; idx += 256) {
    int r = idx >> 5, c = idx & 31;
    float mu = s_out[r][c];
    float lv = s_out[r][c + 32];
    int row = rb + r;
    float elv = expf(lv);
    g_z[(size_t)row * LQ + c] =
        mu + eps_z[(size_t)row * LQ + c] * expf(0.5f * lv);
    kl += 0.5f * (mu * mu + elv - logf(1e-8f + elv) - 1.f);
  }
  __shared__ float sred[256];
  sred[tid] = kl;
  __syncthreads();
  for (int s = 128; s > 0; s >>= 1) {
    if (tid < s) sred[tid] += sred[tid + s];
    __syncthreads();
  }
  if (tid == 0) g_klpart[blockIdx.x] = sred[0];
}

// ---------------------------------------------------------------------------
// GEMM3: g_hd = relu(z @ W_d1^T + b_d1)   M=B, K=32, N=392
// ---------------------------------------------------------------------------
__global__ __launch_bounds__(256) void k_gemm3(
    const float* __restrict__ W, const float* __restrict__ bias) {
  const int K = LQ, N = HQ;
  __shared__ float As[16][64];
  __shared__ float Ws[16][64];
  const int rb = blockIdx.x * 64;
  const int nb = blockIdx.y * 64;
  const int tid = threadIdx.x;
  const int tx = tid & 15, ty = tid >> 4;
  const int lm = tid >> 2;
  const int kq = (tid & 3) * 4;
  float acc[4][4] = {};
  for (int k0 = 0; k0 < K; k0 += 16) {
#pragma unroll
    for (int i = 0; i < 4; i++) {
      int k = k0 + kq + i;
      As[kq + i][lm] = g_z[(size_t)(rb + lm) * K + k];
      float wv = 0.f;
      int n = nb + lm;
      if (n < N) wv = W[(size_t)n * K + k];
      Ws[kq + i][lm] = wv;
    }
    __syncthreads();
#pragma unroll
    for (int kk = 0; kk < 16; kk++) {
      float a[4], w[4];
#pragma unroll
      for (int i = 0; i < 4; i++) a[i] = As[kk][ty * 4 + i];
#pragma unroll
      for (int j = 0; j < 4; j++) w[j] = Ws[kk][tx * 4 + j];
#pragma unroll
      for (int i = 0; i < 4; i++)
#pragma unroll
        for (int j = 0; j < 4; j++) acc[i][j] += a[i] * w[j];
    }
    __syncthreads();
  }
#pragma unroll
  for (int i = 0; i < 4; i++) {
    int r = rb + ty * 4 + i;
#pragma unroll
    for (int j = 0; j < 4; j++) {
      int n = nb + tx * 4 + j;
      if (n < N) g_hd[(size_t)r * N + n] = fmaxf(acc[i][j] + bias[n], 0.f);
    }
  }
}

// ---------------------------------------------------------------------------
// GEMM4: dual GEMM mu_y / lv_y from g_hd (K=392, N=784).
// Tile 256x32, BK=16, 256 thr, microtile 8 rows x 4 cols x 2 matrices (FFMA2).
// Fused epilogue: image = sigmoid(mu + eps_y*exp(.5 lv)) -> out
// plus per (row, n-tile) partials of quad and logdet.
// ---------------------------------------------------------------------------
__global__ __launch_bounds__(256, 2) void k_gemm4(
    const float* __restrict__ Wmu, const float* __restrict__ bmu,
    const float* __restrict__ Wlv, const float* __restrict__ blv,
    const float* __restrict__ x, const float* __restrict__ eps_y,
    float* __restrict__ out) {
  __shared__ __align__(16) float As[16][256];
  __shared__ __align__(16) float Wm[16][32];
  __shared__ __align__(16) float Wl[16][32];
  __shared__ float sq[256][8];
  __shared__ float sl[256][8];
  const int tid = threadIdx.x;
  const int rb = blockIdx.x * 256;
  const int nb = blockIdx.y * 32;
  const int tx = tid & 7, ty = tid >> 3;

  ull accM[8][2] = {};
  ull accL[8][2] = {};
  const float4* Arow = (const float4*)(g_hd + (size_t)(rb + tid) * HQ);
  const int wn = tid >> 3;          // 0..31
  const int wkc = (tid & 7) * 2;    // 0,2,..,14
  const bool wnv = (nb + wn) < DQ;

  for (int k0 = 0; k0 < HQ; k0 += 16) {  // 25 tiles, last partial (392=24*16+8)
    // stage A
#pragma unroll
    for (int c = 0; c < 4; c++) {
      int k = k0 + c * 4;
      float4 v = make_float4(0.f, 0.f, 0.f, 0.f);
      if (k < HQ) v = Arow[k >> 2];
      As[c * 4 + 0][tid] = v.x;
      As[c * 4 + 1][tid] = v.y;
      As[c * 4 + 2][tid] = v.z;
      As[c * 4 + 3][tid] = v.w;
    }
    // stage W (both matrices)
    {
      int k = k0 + wkc;
      float2 vm = make_float2(0.f, 0.f), vl = make_float2(0.f, 0.f);
      if (wnv && k < HQ) {
        vm = *(const float2*)(Wmu + (size_t)(nb + wn) * HQ + k);
        vl = *(const float2*)(Wlv + (size_t)(nb + wn) * HQ + k);
      }
      Wm[wkc + 0][wn] = vm.x;
      Wm[wkc + 1][wn] = vm.y;
      Wl[wkc + 0][wn] = vl.x;
      Wl[wkc + 1][wn] = vl.y;
    }
    __syncthreads();
#pragma unroll
    for (int kk = 0; kk < 16; kk++) {
      float4 a0 = *(const float4*)&As[kk][ty * 8];
      float4 a1 = *(const float4*)&As[kk][ty * 8 + 4];
      ull ad[8];
      ad[0] = dup2(a0.x); ad[1] = dup2(a0.y);
      ad[2] = dup2(a0.z); ad[3] = dup2(a0.w);
      ad[4] = dup2(a1.x); ad[5] = dup2(a1.y);
      ad[6] = dup2(a1.z); ad[7] = dup2(a1.w);
      ull wm[2], wl[2];
#pragma unroll
      for (int j = 0; j < 2; j++) {
        wm[j] = *(const ull*)&Wm[kk][tx * 4 + 2 * j];
        wl[j] = *(const ull*)&Wl[kk][tx * 4 + 2 * j];
      }
#pragma unroll
      for (int i = 0; i < 8; i++)
#pragma unroll
        for (int j = 0; j < 2; j++) {
          accM[i][j] = ffma2(ad[i], wm[j], accM[i][j]);
          accL[i][j] = ffma2(ad[i], wl[j], accL[i][j]);
        }
    }
    __syncthreads();
  }
  // epilogue
#pragma unroll
  for (int i = 0; i < 8; i++) {
    size_t row = rb + ty * 8 + i;
    float q = 0.f, l = 0.f;
#pragma unroll
    for (int j = 0; j < 2; j++) {
      float2 m2 = unpack2(accM[i][j]);
      float2 v2 = unpack2(accL[i][j]);
#pragma unroll
      for (int h = 0; h < 2; h++) {
        int n = nb + tx * 4 + 2 * j + h;
        if (n < DQ) {
          float mu = fmaxf((h ? m2.y : m2.x) + bmu[n], 0.f);
          float lv = fmaxf((h ? v2.y : v2.x) + blv[n], 0.f);
          float s = expf(0.5f * lv);
          size_t off = row * DQ + n;
          float t = mu + eps_y[off] * s;
          out[off] = 1.f / (1.f + expf(-t));
          float d = x[off] - mu;
          q += d * d / s;
          l += 0.5f * lv;
        }
      }
    }
    sq[ty * 8 + i][tx] = q;
    sl[ty * 8 + i][tx] = l;
  }
  __syncthreads();
  {
    float q = 0.f, l = 0.f;
#pragma unroll
    for (int t = 0; t < 8; t++) {
      q += sq[tid][t];
      l += sl[tid][t];
    }
    g_quadpart[(size_t)(rb + tid) * NT4 + blockIdx.y] = q;
    g_ldpart[(size_t)(rb + tid) * NT4 + blockIdx.y] = l;
  }
}

// ---------------------------------------------------------------------------
// Row reduction: per-row log_prob, then per-block partial sum.
// ---------------------------------------------------------------------------
__global__ __launch_bounds__(256) void k_reduce_rows() {
  int row = blockIdx.x * 256 + threadIdx.x;
  float q = 0.f, l = 0.f;
#pragma unroll
  for (int t = 0; t < NT4; t++) {
    q += g_quadpart[(size_t)row * NT4 + t];
    l += g_ldpart[(size_t)row * NT4 + t];
  }
  float lp = -0.5f * (784.f * 1.8378770664093453f + l + q);
  __shared__ float sred[256];
  sred[threadIdx.x] = lp;
  __syncthreads();
  for (int s = 128; s > 0; s >>= 1) {
    if (threadIdx.x < s) sred[threadIdx.x] += sred[threadIdx.x + s];
    __syncthreads();
  }
  if (threadIdx.x == 0) g_lppart[blockIdx.x] = sred[0];
}

// ---------------------------------------------------------------------------
// Final scalar: loss = -mean(log_prob) + KL_total -> out[B*D]
// ---------------------------------------------------------------------------
__global__ __launch_bounds__(256) void k_final(float* __restrict__ out,
                                               int out_size) {
  __shared__ double sd[256];
  int tid = threadIdx.x;
  sd[tid] = (double)g_lppart[tid];
  __syncthreads();
  for (int s = 128; s > 0; s >>= 1) {
    if (tid < s) sd[tid] += sd[tid + s];
    __syncthreads();
  }
  double lp_sum = sd[0];
  __syncthreads();
  double kl = 0.0;
  for (int i = tid; i < NB1; i += 256) kl += (double)g_klpart[i];
  sd[tid] = kl;
  __syncthreads();
  for (int s = 128; s > 0; s >>= 1) {
    if (tid < s) sd[tid] += sd[tid + s];
    __syncthreads();
  }
  if (tid == 0) {
    long long nimg = (long long)BQ * DQ;
    if ((long long)out_size > nimg) {
      out[(size_t)nimg] = (float)(-(lp_sum) / (double)BQ + sd[0]);
    }
  }
}

// ---------------------------------------------------------------------------
extern "C" void kernel_launch(void* const* d_in, const int* in_sizes, int n_in,
                              void* d_out, int out_size) {
  const float* x     = (const float*)d_in[0];
  const float* eps_z = (const float*)d_in[1];
  const float* eps_y = (const float*)d_in[2];
  const float* W_e1  = (const float*)d_in[3];
  const float* b_e1  = (const float*)d_in[4];
  const float* W_emu = (const float*)d_in[5];
  const float* b_emu = (const float*)d_in[6];
  const float* W_elv = (const float*)d_in[7];
  const float* b_elv = (const float*)d_in[8];
  const float* W_d1  = (const float*)d_in[9];
  const float* b_d1  = (const float*)d_in[10];
  const float* W_dmu = (const float*)d_in[11];
  const float* b_dmu = (const float*)d_in[12];
  const float* W_dlv = (const float*)d_in[13];
  const float* b_dlv = (const float*)d_in[14];
  float* out = (float*)d_out;

  dim3 blk(256);
  k_gemm1<<<dim3(BQ / 256, (HQ + 63) / 64), blk>>>(x, W_e1, b_e1);
  k_gemm2<<<dim3(NB1, 1), blk>>>(W_emu, b_emu, W_elv, b_elv, eps_z);
  k_gemm3<<<dim3(NB1, (HQ + 63) / 64), blk>>>(W_d1, b_d1);
  k_gemm4<<<dim3(BQ / 256, NT4), blk>>>(W_dmu, b_dmu, W_dlv, b_dlv, x, eps_y,
                                        out);
  k_reduce_rows<<<NRED, blk>>>();
  k_final<<<1, blk>>>(out, out_size);
}

// round 4
// speedup vs baseline: 2.4675x; 1.9537x over previous
#include <cuda_runtime.h>
#include <math.h>
#include <stdint.h>

// Problem constants
#define BQ 65536
#define DQ 784
#define HQ 392
#define LQ 32
#define NT4 13                 // ceil(784/64) N-tiles in gemm4
#define NB1 ((BQ) / 64)        // row blocks for gemm2/3
#define NRED 256
#define SSTR 36                // smem row stride (floats), pad-4 conflict-free

// Scratch
__device__ float g_h[(size_t)BQ * HQ];
__device__ float g_z[(size_t)BQ * LQ];
__device__ float g_hd[(size_t)BQ * HQ];
__device__ float g_quadpart[(size_t)BQ * NT4];
__device__ float g_ldpart[(size_t)BQ * NT4];
__device__ float g_klpart[NB1];
__device__ float g_lppart[NRED];

// ---------------------------------------------------------------------------
// helpers
// ---------------------------------------------------------------------------
__device__ __forceinline__ uint32_t smem_u32(const void* p) {
  uint32_t a;
  asm("{ .reg .u64 t; cvta.to.shared.u64 t, %1; cvt.u32.u64 %0, t; }"
      : "=r"(a) : "l"(p));
  return a;
}
__device__ __forceinline__ uint32_t f2tf32(float f) {
  uint32_t r;
  asm("cvt.rna.tf32.f32 %0, %1;" : "=r"(r) : "f"(f));
  return r;
}
__device__ __forceinline__ void cp16(uint32_t dst, const void* src,
                                     uint32_t sz) {
  asm volatile("cp.async.cg.shared.global [%0], [%1], 16, %2;"
               :: "r"(dst), "l"(__cvta_generic_to_global(src)), "r"(sz));
}
#define CP_COMMIT() asm volatile("cp.async.commit_group;" ::: "memory")
template <int N>
__device__ __forceinline__ void cp_wait() {
  asm volatile("cp.async.wait_group %0;" :: "n"(N) : "memory");
}
__device__ __forceinline__ void mma8(float* d, const uint32_t* a,
                                     const uint32_t* b) {
  asm volatile(
      "mma.sync.aligned.m16n8k8.row.col.f32.tf32.tf32.f32 "
      "{%0,%1,%2,%3}, {%4,%5,%6,%7}, {%8,%9}, {%0,%1,%2,%3};"
      : "+f"(d[0]), "+f"(d[1]), "+f"(d[2]), "+f"(d[3])
      : "r"(a[0]), "r"(a[1]), "r"(a[2]), "r"(a[3]), "r"(b[0]), "r"(b[1]));
}

// ---------------------------------------------------------------------------
// K1 (tf32 mma): g_h = relu(x @ W_e1^T + b_e1)   M=B, N=392, K=784
// Block tile 128x64, BK=32, 256 thr (8 warps 4Mx2N), warp tile 32x32.
// ---------------------------------------------------------------------------
#define K1_NIT 25
__global__ __launch_bounds__(256) void k1_mma(const float* __restrict__ A,
                                              const float* __restrict__ W,
                                              const float* __restrict__ bias) {
  extern __shared__ float sm[];
  const uint32_t sbase = smem_u32(sm);
  const int tid = threadIdx.x;
  const int lane = tid & 31, wid = tid >> 5;
  const int wm = wid & 3, wn = wid >> 2;
  const int qr = lane >> 2, qc = lane & 3;
  const int rb = blockIdx.y * 128;
  const int nb = blockIdx.x * 64;
  // staging roles
  const int ar = tid >> 1, ac4 = (tid & 1) * 4;
  const int wr = tid >> 2, wc4 = (tid & 3) * 2;

  float acc[2][4][4] = {};

  auto stage = [&](int t) {
    const int k0 = t * 32;
    const uint32_t abase = sbase + ((t & 1) ? 4608u : 0u) * 4u;
    const uint32_t wbase = sbase + (9216u + ((t & 1) ? 2304u : 0u)) * 4u;
    const float* gA = A + (size_t)(rb + ar) * DQ + k0;
#pragma unroll
    for (int i = 0; i < 4; i++) {
      int c4 = ac4 + i;
      uint32_t sz = (k0 + c4 * 4 < DQ) ? 16u : 0u;
      cp16(abase + (uint32_t)(ar * SSTR + c4 * 4) * 4u, gA + c4 * 4, sz);
    }
    const int n = nb + wr;
    const float* gW = W + (size_t)((n < HQ) ? n : 0) * DQ + k0;
#pragma unroll
    for (int i = 0; i < 2; i++) {
      int c4 = wc4 + i;
      uint32_t sz = ((n < HQ) && (k0 + c4 * 4 < DQ)) ? 16u : 0u;
      cp16(wbase + (uint32_t)(wr * SSTR + c4 * 4) * 4u, gW + c4 * 4, sz);
    }
  };

  stage(0);
  CP_COMMIT();
  for (int it = 0; it < K1_NIT; ++it) {
    if (it + 1 < K1_NIT) {
      stage(it + 1);
      CP_COMMIT();
      cp_wait<1>();
    } else {
      cp_wait<0>();
    }
    __syncthreads();
    const float* Ab = sm + ((it & 1) ? 4608 : 0);
    const float* Wb = sm + 9216 + ((it & 1) ? 2304 : 0);
#pragma unroll
    for (int kk = 0; kk < 4; kk++) {
      uint32_t af[2][4];
#pragma unroll
      for (int i = 0; i < 2; i++) {
        const float* p = Ab + (wm * 32 + i * 16 + qr) * SSTR + kk * 8 + qc;
        af[i][0] = f2tf32(p[0]);
        af[i][1] = f2tf32(p[8 * SSTR]);
        af[i][2] = f2tf32(p[4]);
        af[i][3] = f2tf32(p[8 * SSTR + 4]);
      }
      uint32_t bf[4][2];
#pragma unroll
      for (int j = 0; j < 4; j++) {
        const float* p = Wb + (wn * 32 + j * 8 + qr) * SSTR + kk * 8 + qc;
        bf[j][0] = f2tf32(p[0]);
        bf[j][1] = f2tf32(p[4]);
      }
#pragma unroll
      for (int i = 0; i < 2; i++)
#pragma unroll
        for (int j = 0; j < 4; j++) mma8(acc[i][j], af[i], bf[j]);
    }
    __syncthreads();
  }
  // epilogue: relu + bias, coalesced-ish float2 stores
#pragma unroll
  for (int i = 0; i < 2; i++) {
    int r0 = rb + wm * 32 + i * 16 + qr;
#pragma unroll
    for (int j = 0; j < 4; j++) {
      int col = nb + wn * 32 + j * 8 + qc * 2;
      if (col < HQ) {
        float b0 = bias[col], b1 = bias[col + 1];
        float2 v0 = make_float2(fmaxf(acc[i][j][0] + b0, 0.f),
                                fmaxf(acc[i][j][1] + b1, 0.f));
        float2 v1 = make_float2(fmaxf(acc[i][j][2] + b0, 0.f),
                                fmaxf(acc[i][j][3] + b1, 0.f));
        *(float2*)&g_h[(size_t)r0 * HQ + col] = v0;
        *(float2*)&g_h[(size_t)(r0 + 8) * HQ + col] = v1;
      }
    }
  }
}

// ---------------------------------------------------------------------------
// K4 (tf32 mma, dual): mu_y/lv_y = relu(g_hd @ W^T + b) for both W_dmu/W_dlv
// Block tile 128x64, BK=32; fused sigmoid/out + quad/logdet partials.
// ---------------------------------------------------------------------------
#define K4_NIT 13
__global__ __launch_bounds__(256) void k4_mma(
    const float* __restrict__ Wmu, const float* __restrict__ bmu,
    const float* __restrict__ Wlv, const float* __restrict__ blv,
    const float* __restrict__ x, const float* __restrict__ eps_y,
    float* __restrict__ out) {
  extern __shared__ float sm[];
  const uint32_t sbase = smem_u32(sm);
  const int tid = threadIdx.x;
  const int lane = tid & 31, wid = tid >> 5;
  const int wm = wid & 3, wn = wid >> 2;
  const int qr = lane >> 2, qc = lane & 3;
  const int rb = blockIdx.y * 128;
  const int nb = blockIdx.x * 64;
  const int ar = tid >> 1, ac4 = (tid & 1) * 4;
  const int wr = tid >> 2, wc4 = (tid & 3) * 2;

  float accM[2][4][4] = {};
  float accL[2][4][4] = {};

  auto stage = [&](int t) {
    const int k0 = t * 32;
    const uint32_t abase = sbase + ((t & 1) ? 4608u : 0u) * 4u;
    const uint32_t mbase = sbase + (9216u + ((t & 1) ? 2304u : 0u)) * 4u;
    const uint32_t lbase = sbase + (13824u + ((t & 1) ? 2304u : 0u)) * 4u;
    const float* gA = g_hd + (size_t)(rb + ar) * HQ + k0;
#pragma unroll
    for (int i = 0; i < 4; i++) {
      int c4 = ac4 + i;
      uint32_t sz = (k0 + c4 * 4 < HQ) ? 16u : 0u;
      cp16(abase + (uint32_t)(ar * SSTR + c4 * 4) * 4u, gA + c4 * 4, sz);
    }
    const int n = nb + wr;
    const size_t wo = (size_t)((n < DQ) ? n : 0) * HQ + k0;
#pragma unroll
    for (int i = 0; i < 2; i++) {
      int c4 = wc4 + i;
      uint32_t sz = ((n < DQ) && (k0 + c4 * 4 < HQ)) ? 16u : 0u;
      uint32_t so = (uint32_t)(wr * SSTR + c4 * 4) * 4u;
      cp16(mbase + so, Wmu + wo + c4 * 4, sz);
      cp16(lbase + so, Wlv + wo + c4 * 4, sz);
    }
  };

  stage(0);
  CP_COMMIT();
  for (int it = 0; it < K4_NIT; ++it) {
    if (it + 1 < K4_NIT) {
      stage(it + 1);
      CP_COMMIT();
      cp_wait<1>();
    } else {
      cp_wait<0>();
    }
    __syncthreads();
    const float* Ab = sm + ((it & 1) ? 4608 : 0);
    const float* Mb = sm + 9216 + ((it & 1) ? 2304 : 0);
    const float* Lb = sm + 13824 + ((it & 1) ? 2304 : 0);
#pragma unroll
    for (int kk = 0; kk < 4; kk++) {
      uint32_t af[2][4];
#pragma unroll
      for (int i = 0; i < 2; i++) {
        const float* p = Ab + (wm * 32 + i * 16 + qr) * SSTR + kk * 8 + qc;
        af[i][0] = f2tf32(p[0]);
        af[i][1] = f2tf32(p[8 * SSTR]);
        af[i][2] = f2tf32(p[4]);
        af[i][3] = f2tf32(p[8 * SSTR + 4]);
      }
      uint32_t bm[4][2], bl[4][2];
#pragma unroll
      for (int j = 0; j < 4; j++) {
        int o = (wn * 32 + j * 8 + qr) * SSTR + kk * 8 + qc;
        bm[j][0] = f2tf32(Mb[o]);
        bm[j][1] = f2tf32(Mb[o + 4]);
        bl[j][0] = f2tf32(Lb[o]);
        bl[j][1] = f2tf32(Lb[o + 4]);
      }
#pragma unroll
      for (int i = 0; i < 2; i++)
#pragma unroll
        for (int j = 0; j < 4; j++) {
          mma8(accM[i][j], af[i], bm[j]);
          mma8(accL[i][j], af[i], bl[j]);
        }
    }
    __syncthreads();
  }

  // epilogue: sigmoid/out + deterministic row partials
  float* srq = sm + 18432;  // [128][2]
  float* srl = sm + 18688;  // [128][2]
#pragma unroll
  for (int i = 0; i < 2; i++) {
#pragma unroll
    for (int half = 0; half < 2; half++) {
      const int rlocal = wm * 32 + i * 16 + qr + half * 8;
      const size_t row = rb + rlocal;
      float q = 0.f, l = 0.f;
#pragma unroll
      for (int j = 0; j < 4; j++) {
        int col = nb + wn * 32 + j * 8 + qc * 2;
#pragma unroll
        for (int e = 0; e < 2; e++) {
          int c = col + e;
          if (c < DQ) {
            float mu = fmaxf(accM[i][j][half * 2 + e] + bmu[c], 0.f);
            float lv = fmaxf(accL[i][j][half * 2 + e] + blv[c], 0.f);
            float s = __expf(0.5f * lv);
            size_t off = row * DQ + c;
            float t = mu + eps_y[off] * s;
            out[off] = __fdividef(1.f, 1.f + __expf(-t));
            float d = x[off] - mu;
            q += __fdividef(d * d, s);
            l += 0.5f * lv;
          }
        }
      }
      q += __shfl_xor_sync(0xffffffffu, q, 1);
      q += __shfl_xor_sync(0xffffffffu, q, 2);
      l += __shfl_xor_sync(0xffffffffu, l, 1);
      l += __shfl_xor_sync(0xffffffffu, l, 2);
      if (qc == 0) {
        srq[rlocal * 2 + wn] = q;
        srl[rlocal * 2 + wn] = l;
      }
    }
  }
  __syncthreads();
  if (tid < 128) {
    g_quadpart[(size_t)(rb + tid) * NT4 + blockIdx.x] =
        srq[tid * 2] + srq[tid * 2 + 1];
    g_ldpart[(size_t)(rb + tid) * NT4 + blockIdx.x] =
        srl[tid * 2] + srl[tid * 2 + 1];
  }
}

// ---------------------------------------------------------------------------
// GEMM2 (SIMT): mu_z/lv_z combined N=64, fused reparam + KL partial. K=392.
// ---------------------------------------------------------------------------
__global__ __launch_bounds__(256) void k_gemm2(
    const float* __restrict__ Wmu, const float* __restrict__ bmu,
    const float* __restrict__ Wlv, const float* __restrict__ blv,
    const float* __restrict__ eps_z) {
  const int K = HQ;
  __shared__ float As[16][64];
  __shared__ float Ws[16][64];
  __shared__ float s_out[64][65];
  const int rb = blockIdx.x * 64;
  const int tid = threadIdx.x;
  const int tx = tid & 15, ty = tid >> 4;
  const int lm = tid >> 2;
  const int kq = (tid & 3) * 4;
  float acc[4][4] = {};
  for (int k0 = 0; k0 < K; k0 += 16) {
#pragma unroll
    for (int i = 0; i < 4; i++) {
      int k = k0 + kq + i;
      As[kq + i][lm] = (k < K) ? g_h[(size_t)(rb + lm) * K + k] : 0.f;
      float wv = 0.f;
      if (k < K)
        wv = (lm < 32) ? Wmu[(size_t)lm * K + k]
                       : Wlv[(size_t)(lm - 32) * K + k];
      Ws[kq + i][lm] = wv;
    }
    __syncthreads();
#pragma unroll
    for (int kk = 0; kk < 16; kk++) {
      float a[4], w[4];
#pragma unroll
      for (int i = 0; i < 4; i++) a[i] = As[kk][ty * 4 + i];
#pragma unroll
      for (int j = 0; j < 4; j++) w[j] = Ws[kk][tx * 4 + j];
#pragma unroll
      for (int i = 0; i < 4; i++)
#pragma unroll
        for (int j = 0; j < 4; j++) acc[i][j] += a[i] * w[j];
    }
    __syncthreads();
  }
#pragma unroll
  for (int i = 0; i < 4; i++)
#pragma unroll
    for (int j = 0; j < 4; j++) {
      int c = tx * 4 + j;
      float b = (c < 32) ? bmu[c] : blv[c - 32];
      s_out[ty * 4 + i][c] = fmaxf(acc[i][j] + b, 0.f);
    }
  __syncthreads();
  float kl = 0.f;
  for (int idx = tid; idx < 64 * 32; idx += 256) {
    int r = idx >> 5, c = idx & 31;
    float mu = s_out[r][c];
    float lv = s_out[r][c + 32];
    int row = rb + r;
    float elv = expf(lv);
    g_z[(size_t)row * LQ + c] =
        mu + eps_z[(size_t)row * LQ + c] * expf(0.5f * lv);
    kl += 0.5f * (mu * mu + elv - logf(1e-8f + elv) - 1.f);
  }
  __shared__ float sred[256];
  sred[tid] = kl;
  __syncthreads();
  for (int s = 128; s > 0; s >>= 1) {
    if (tid < s) sred[tid] += sred[tid + s];
    __syncthreads();
  }
  if (tid == 0) g_klpart[blockIdx.x] = sred[0];
}

// ---------------------------------------------------------------------------
// GEMM3 (SIMT): g_hd = relu(z @ W_d1^T + b_d1)   K=32, N=392
// ---------------------------------------------------------------------------
__global__ __launch_bounds__(256) void k_gemm3(
    const float* __restrict__ W, const float* __restrict__ bias) {
  const int K = LQ, N = HQ;
  __shared__ float As[16][64];
  __shared__ float Ws[16][64];
  const int rb = blockIdx.x * 64;
  const int nb = blockIdx.y * 64;
  const int tid = threadIdx.x;
  const int tx = tid & 15, ty = tid >> 4;
  const int lm = tid >> 2;
  const int kq = (tid & 3) * 4;
  float acc[4][4] = {};
  for (int k0 = 0; k0 < K; k0 += 16) {
#pragma unroll
    for (int i = 0; i < 4; i++) {
      int k = k0 + kq + i;
      As[kq + i][lm] = g_z[(size_t)(rb + lm) * K + k];
      float wv = 0.f;
      int n = nb + lm;
      if (n < N) wv = W[(size_t)n * K + k];
      Ws[kq + i][lm] = wv;
    }
    __syncthreads();
#pragma unroll
    for (int kk = 0; kk < 16; kk++) {
      float a[4], w[4];
#pragma unroll
      for (int i = 0; i < 4; i++) a[i] = As[kk][ty * 4 + i];
#pragma unroll
      for (int j = 0; j < 4; j++) w[j] = Ws[kk][tx * 4 + j];
#pragma unroll
      for (int i = 0; i < 4; i++)
#pragma unroll
        for (int j = 0; j < 4; j++) acc[i][j] += a[i] * w[j];
    }
    __syncthreads();
  }
#pragma unroll
  for (int i = 0; i < 4; i++) {
    int r = rb + ty * 4 + i;
#pragma unroll
    for (int j = 0; j < 4; j++) {
      int n = nb + tx * 4 + j;
      if (n < N) g_hd[(size_t)r * N + n] = fmaxf(acc[i][j] + bias[n], 0.f);
    }
  }
}

// ---------------------------------------------------------------------------
// Row reduction + final scalar
// ---------------------------------------------------------------------------
__global__ __launch_bounds__(256) void k_reduce_rows() {
  int row = blockIdx.x * 256 + threadIdx.x;
  float q = 0.f, l = 0.f;
#pragma unroll
  for (int t = 0; t < NT4; t++) {
    q += g_quadpart[(size_t)row * NT4 + t];
    l += g_ldpart[(size_t)row * NT4 + t];
  }
  float lp = -0.5f * (784.f * 1.8378770664093453f + l + q);
  __shared__ float sred[256];
  sred[threadIdx.x] = lp;
  __syncthreads();
  for (int s = 128; s > 0; s >>= 1) {
    if (threadIdx.x < s) sred[threadIdx.x] += sred[threadIdx.x + s];
    __syncthreads();
  }
  if (threadIdx.x == 0) g_lppart[blockIdx.x] = sred[0];
}

__global__ __launch_bounds__(256) void k_final(float* __restrict__ out,
                                               int out_size) {
  __shared__ double sd[256];
  int tid = threadIdx.x;
  sd[tid] = (double)g_lppart[tid];
  __syncthreads();
  for (int s = 128; s > 0; s >>= 1) {
    if (tid < s) sd[tid] += sd[tid + s];
    __syncthreads();
  }
  double lp_sum = sd[0];
  __syncthreads();
  double kl = 0.0;
  for (int i = tid; i < NB1; i += 256) kl += (double)g_klpart[i];
  sd[tid] = kl;
  __syncthreads();
  for (int s = 128; s > 0; s >>= 1) {
    if (tid < s) sd[tid] += sd[tid + s];
    __syncthreads();
  }
  if (tid == 0) {
    long long nimg = (long long)BQ * DQ;
    if ((long long)out_size > nimg)
      out[(size_t)nimg] = (float)(-(lp_sum) / (double)BQ + sd[0]);
  }
}

// ---------------------------------------------------------------------------
extern "C" void kernel_launch(void* const* d_in, const int* in_sizes, int n_in,
                              void* d_out, int out_size) {
  const float* x     = (const float*)d_in[0];
  const float* eps_z = (const float*)d_in[1];
  const float* eps_y = (const float*)d_in[2];
  const float* W_e1  = (const float*)d_in[3];
  const float* b_e1  = (const float*)d_in[4];
  const float* W_emu = (const float*)d_in[5];
  const float* b_emu = (const float*)d_in[6];
  const float* W_elv = (const float*)d_in[7];
  const float* b_elv = (const float*)d_in[8];
  const float* W_d1  = (const float*)d_in[9];
  const float* b_d1  = (const float*)d_in[10];
  const float* W_dmu = (const float*)d_in[11];
  const float* b_dmu = (const float*)d_in[12];
  const float* W_dlv = (const float*)d_in[13];
  const float* b_dlv = (const float*)d_in[14];
  float* out = (float*)d_out;

  cudaFuncSetAttribute(k1_mma, cudaFuncAttributeMaxDynamicSharedMemorySize,
                       55296);
  cudaFuncSetAttribute(k4_mma, cudaFuncAttributeMaxDynamicSharedMemorySize,
                       75776);

  k1_mma<<<dim3(7, BQ / 128), 256, 55296>>>(x, W_e1, b_e1);
  k_gemm2<<<dim3(NB1, 1), 256>>>(W_emu, b_emu, W_elv, b_elv, eps_z);
  k_gemm3<<<dim3(NB1, 7), 256>>>(W_d1, b_d1);
  k4_mma<<<dim3(NT4, BQ / 128), 256, 75776>>>(W_dmu, b_dmu, W_dlv, b_dlv, x,
                                              eps_y, out);
  k_reduce_rows<<<NRED, 256>>>();
  k_final<<<1, 256>>>(out, out_size);
}

// round 6
// speedup vs baseline: 2.6214x; 1.0624x over previous
#include <cuda_runtime.h>
#include <math.h>
#include <stdint.h>

// Problem constants
#define BQ 65536
#define DQ 784
#define HQ 392
#define LQ 32
#define NT4 13                 // ceil(784/64) N-tiles in gemm4
#define NB1 ((BQ) / 64)        // row blocks for gemm2/3
#define NRED 256
#define SSTR 36                // smem row stride (floats), pad-4 conflict-free

// Scratch
__device__ float g_h[(size_t)BQ * HQ];
__device__ float g_z[(size_t)BQ * LQ];
__device__ float g_hd[(size_t)BQ * HQ];
__device__ float g_xtf[(size_t)BQ * DQ];     // rna(x) for k1 A operand
__device__ float g_we1[(size_t)HQ * DQ];     // rna(W_e1)
__device__ float g_wdmu[(size_t)DQ * HQ];    // rna(W_dmu)
__device__ float g_wdlv[(size_t)DQ * HQ];    // rna(W_dlv)
__device__ float g_quadpart[(size_t)BQ * NT4];
__device__ float g_ldpart[(size_t)BQ * NT4];
__device__ float g_klpart[NB1];
__device__ float g_lppart[NRED];

// ---------------------------------------------------------------------------
// helpers
// ---------------------------------------------------------------------------
__device__ __forceinline__ void cp16(uint32_t dst, const void* src,
                                     uint32_t sz) {
  asm volatile("cp.async.cg.shared.global [%0], [%1], 16, %2;"
               :: "r"(dst), "l"(__cvta_generic_to_global(src)), "r"(sz));
}
#define CP_COMMIT() asm volatile("cp.async.commit_group;" ::: "memory")
template <int N>
__device__ __forceinline__ void cp_wait() {
  asm volatile("cp.async.wait_group %0;" :: "n"(N) : "memory");
}
__device__ __forceinline__ uint32_t smem_u32(const void* p) {
  uint32_t a;
  asm("{ .reg .u64 t; cvta.to.shared.u64 t, %1; cvt.u32.u64 %0, t; }"
      : "=r"(a) : "l"(p));
  return a;
}
__device__ __forceinline__ float rna(float f) {
  uint32_t r;
  asm("cvt.rna.tf32.f32 %0, %1;" : "=r"(r) : "f"(f));
  return __uint_as_float(r);
}
// tf32 mma with raw fp32 bits (inputs pre-rounded with rna by producers)
__device__ __forceinline__ void mma8(float* d, const float* a, const float* b) {
  asm volatile(
      "mma.sync.aligned.m16n8k8.row.col.f32.tf32.tf32.f32 "
      "{%0,%1,%2,%3}, {%4,%5,%6,%7}, {%8,%9}, {%0,%1,%2,%3};"
      : "+f"(d[0]), "+f"(d[1]), "+f"(d[2]), "+f"(d[3])
      : "r"(__float_as_uint(a[0])), "r"(__float_as_uint(a[1])),
        "r"(__float_as_uint(a[2])), "r"(__float_as_uint(a[3])),
        "r"(__float_as_uint(b[0])), "r"(__float_as_uint(b[1])));
}

// ---------------------------------------------------------------------------
// rna pre-rounding copy (float4 grid-stride)
// ---------------------------------------------------------------------------
__global__ __launch_bounds__(256) void k_cvt(const float4* __restrict__ src,
                                             float4* __restrict__ dst,
                                             int n4) {
  int i = blockIdx.x * 256 + threadIdx.x;
  int stride = gridDim.x * 256;
  for (; i < n4; i += stride) {
    float4 v = src[i];
    v.x = rna(v.x);
    v.y = rna(v.y);
    v.z = rna(v.z);
    v.w = rna(v.w);
    dst[i] = v;
  }
}

// ---------------------------------------------------------------------------
// K1 (tf32 mma): g_h = relu(x @ W_e1^T + b_e1)   M=B, N=392, K=784
// Block tile 128x64, BK=32, 256 thr (8 warps 4Mx2N), 3-stage cp.async ring.
// ---------------------------------------------------------------------------
#define K1_NIT 25
__global__ __launch_bounds__(256, 2) void k1_mma(
    const float* __restrict__ A, const float* __restrict__ W,
    const float* __restrict__ bias) {
  extern __shared__ float sm[];
  const uint32_t sbase = smem_u32(sm);
  const int tid = threadIdx.x;
  const int lane = tid & 31, wid = tid >> 5;
  const int wm = wid & 3, wn = wid >> 2;
  const int qr = lane >> 2, qc = lane & 3;
  const int rb = blockIdx.y * 128;
  const int nb = blockIdx.x * 64;
  const int ar = tid >> 1, ac4 = (tid & 1) * 4;
  const int wr = tid >> 2, wc4 = (tid & 3) * 2;

  float acc[2][4][4] = {};

  auto stage = [&](int t) {
    const int s3 = t % 3;
    const int k0 = t * 32;
    const uint32_t abase = sbase + (uint32_t)(s3 * 4608) * 4u;
    const uint32_t wbase = sbase + (uint32_t)(13824 + s3 * 2304) * 4u;
    const float* gA = A + (size_t)(rb + ar) * DQ + k0;
#pragma unroll
    for (int i = 0; i < 4; i++) {
      int c4 = ac4 + i;
      uint32_t sz = (k0 + c4 * 4 < DQ) ? 16u : 0u;
      cp16(abase + (uint32_t)(ar * SSTR + c4 * 4) * 4u, gA + c4 * 4, sz);
    }
    const int n = nb + wr;
    const float* gW = W + (size_t)((n < HQ) ? n : 0) * DQ + k0;
#pragma unroll
    for (int i = 0; i < 2; i++) {
      int c4 = wc4 + i;
      uint32_t sz = ((n < HQ) && (k0 + c4 * 4 < DQ)) ? 16u : 0u;
      cp16(wbase + (uint32_t)(wr * SSTR + c4 * 4) * 4u, gW + c4 * 4, sz);
    }
  };

  stage(0);
  CP_COMMIT();
  stage(1);
  CP_COMMIT();
  for (int it = 0; it < K1_NIT; ++it) {
    if (it + 1 < K1_NIT) cp_wait<1>();
    else cp_wait<0>();
    __syncthreads();
    if (it + 2 < K1_NIT) {
      stage(it + 2);
      CP_COMMIT();
    }
    const int s3 = it % 3;
    const float* Ab = sm + s3 * 4608;
    const float* Wb = sm + 13824 + s3 * 2304;
#pragma unroll
    for (int kk = 0; kk < 4; kk++) {
      float af[2][4];
#pragma unroll
      for (int i = 0; i < 2; i++) {
        const float* p = Ab + (wm * 32 + i * 16 + qr) * SSTR + kk * 8 + qc;
        af[i][0] = p[0];
        af[i][1] = p[8 * SSTR];
        af[i][2] = p[4];
        af[i][3] = p[8 * SSTR + 4];
      }
      float bf[4][2];
#pragma unroll
      for (int j = 0; j < 4; j++) {
        const float* p = Wb + (wn * 32 + j * 8 + qr) * SSTR + kk * 8 + qc;
        bf[j][0] = p[0];
        bf[j][1] = p[4];
      }
#pragma unroll
      for (int i = 0; i < 2; i++)
#pragma unroll
        for (int j = 0; j < 4; j++) mma8(acc[i][j], af[i], bf[j]);
    }
  }
  // epilogue: relu + bias
#pragma unroll
  for (int i = 0; i < 2; i++) {
    int r0 = rb + wm * 32 + i * 16 + qr;
#pragma unroll
    for (int j = 0; j < 4; j++) {
      int col = nb + wn * 32 + j * 8 + qc * 2;
      if (col < HQ) {
        float b0 = bias[col], b1 = bias[col + 1];
        float2 v0 = make_float2(fmaxf(acc[i][j][0] + b0, 0.f),
                                fmaxf(acc[i][j][1] + b1, 0.f));
        float2 v1 = make_float2(fmaxf(acc[i][j][2] + b0, 0.f),
                                fmaxf(acc[i][j][3] + b1, 0.f));
        *(float2*)&g_h[(size_t)r0 * HQ + col] = v0;
        *(float2*)&g_h[(size_t)(r0 + 8) * HQ + col] = v1;
      }
    }
  }
}
#define K1_SMEM ((13824 + 3 * 2304) * 4)

// ---------------------------------------------------------------------------
// K4 (tf32 mma, dual): mu_y/lv_y from g_hd; fused sigmoid/out + partials.
// ---------------------------------------------------------------------------
#define K4_NIT 13
__global__ __launch_bounds__(256, 2) void k4_mma(
    const float* __restrict__ Wmu, const float* __restrict__ bmu,
    const float* __restrict__ Wlv, const float* __restrict__ blv,
    const float* __restrict__ x, const float* __restrict__ eps_y,
    float* __restrict__ out) {
  extern __shared__ float sm[];
  const uint32_t sbase = smem_u32(sm);
  const int tid = threadIdx.x;
  const int lane = tid & 31, wid = tid >> 5;
  const int wm = wid & 3, wn = wid >> 2;
  const int qr = lane >> 2, qc = lane & 3;
  const int rb = blockIdx.y * 128;
  const int nb = blockIdx.x * 64;
  const int ar = tid >> 1, ac4 = (tid & 1) * 4;
  const int wr = tid >> 2, wc4 = (tid & 3) * 2;

  float accM[2][4][4] = {};
  float accL[2][4][4] = {};

  auto stage = [&](int t) {
    const int s3 = t % 3;
    const int k0 = t * 32;
    const uint32_t abase = sbase + (uint32_t)(s3 * 4608) * 4u;
    const uint32_t mbase = sbase + (uint32_t)(13824 + s3 * 2304) * 4u;
    const uint32_t lbase = sbase + (uint32_t)(20736 + s3 * 2304) * 4u;
    const float* gA = g_hd + (size_t)(rb + ar) * HQ + k0;
#pragma unroll
    for (int i = 0; i < 4; i++) {
      int c4 = ac4 + i;
      uint32_t sz = (k0 + c4 * 4 < HQ) ? 16u : 0u;
      cp16(abase + (uint32_t)(ar * SSTR + c4 * 4) * 4u, gA + c4 * 4, sz);
    }
    const int n = nb + wr;
    const size_t wo = (size_t)((n < DQ) ? n : 0) * HQ + k0;
#pragma unroll
    for (int i = 0; i < 2; i++) {
      int c4 = wc4 + i;
      uint32_t sz = ((n < DQ) && (k0 + c4 * 4 < HQ)) ? 16u : 0u;
      uint32_t so = (uint32_t)(wr * SSTR + c4 * 4) * 4u;
      cp16(mbase + so, Wmu + wo + c4 * 4, sz);
      cp16(lbase + so, Wlv + wo + c4 * 4, sz);
    }
  };

  stage(0);
  CP_COMMIT();
  stage(1);
  CP_COMMIT();
  for (int it = 0; it < K4_NIT; ++it) {
    if (it + 1 < K4_NIT) cp_wait<1>();
    else cp_wait<0>();
    __syncthreads();
    if (it + 2 < K4_NIT) {
      stage(it + 2);
      CP_COMMIT();
    }
    const int s3 = it % 3;
    const float* Ab = sm + s3 * 4608;
    const float* Mb = sm + 13824 + s3 * 2304;
    const float* Lb = sm + 20736 + s3 * 2304;
#pragma unroll
    for (int kk = 0; kk < 4; kk++) {
      float af[2][4];
#pragma unroll
      for (int i = 0; i < 2; i++) {
        const float* p = Ab + (wm * 32 + i * 16 + qr) * SSTR + kk * 8 + qc;
        af[i][0] = p[0];
        af[i][1] = p[8 * SSTR];
        af[i][2] = p[4];
        af[i][3] = p[8 * SSTR + 4];
      }
      float bm[4][2], bl[4][2];
#pragma unroll
      for (int j = 0; j < 4; j++) {
        int o = (wn * 32 + j * 8 + qr) * SSTR + kk * 8 + qc;
        bm[j][0] = Mb[o];
        bm[j][1] = Mb[o + 4];
        bl[j][0] = Lb[o];
        bl[j][1] = Lb[o + 4];
      }
#pragma unroll
      for (int i = 0; i < 2; i++)
#pragma unroll
        for (int j = 0; j < 4; j++) {
          mma8(accM[i][j], af[i], bm[j]);
          mma8(accL[i][j], af[i], bl[j]);
        }
    }
  }

  // epilogue: sigmoid/out + deterministic row partials
  float* srq = sm + 27648;  // [128][2]
  float* srl = sm + 27904;  // [128][2]
  __syncthreads();
#pragma unroll
  for (int i = 0; i < 2; i++) {
#pragma unroll
    for (int half = 0; half < 2; half++) {
      const int rlocal = wm * 32 + i * 16 + qr + half * 8;
      const size_t row = rb + rlocal;
      float q = 0.f, l = 0.f;
#pragma unroll
      for (int j = 0; j < 4; j++) {
        int col = nb + wn * 32 + j * 8 + qc * 2;
#pragma unroll
        for (int e = 0; e < 2; e++) {
          int c = col + e;
          if (c < DQ) {
            float mu = fmaxf(accM[i][j][half * 2 + e] + bmu[c], 0.f);
            float lv = fmaxf(accL[i][j][half * 2 + e] + blv[c], 0.f);
            float s = __expf(0.5f * lv);
            size_t off = row * DQ + c;
            float t = mu + eps_y[off] * s;
            out[off] = __fdividef(1.f, 1.f + __expf(-t));
            float d = x[off] - mu;
            q += __fdividef(d * d, s);
            l += 0.5f * lv;
          }
        }
      }
      q += __shfl_xor_sync(0xffffffffu, q, 1);
      q += __shfl_xor_sync(0xffffffffu, q, 2);
      l += __shfl_xor_sync(0xffffffffu, l, 1);
      l += __shfl_xor_sync(0xffffffffu, l, 2);
      if (qc == 0) {
        srq[rlocal * 2 + wn] = q;
        srl[rlocal * 2 + wn] = l;
      }
    }
  }
  __syncthreads();
  if (tid < 128) {
    g_quadpart[(size_t)(rb + tid) * NT4 + blockIdx.x] =
        srq[tid * 2] + srq[tid * 2 + 1];
    g_ldpart[(size_t)(rb + tid) * NT4 + blockIdx.x] =
        srl[tid * 2] + srl[tid * 2 + 1];
  }
}
#define K4_SMEM (28160 * 4)

// ---------------------------------------------------------------------------
// GEMM2 (SIMT): mu_z/lv_z combined N=64, fused reparam + KL partial. K=392.
// ---------------------------------------------------------------------------
__global__ __launch_bounds__(256) void k_gemm2(
    const float* __restrict__ Wmu, const float* __restrict__ bmu,
    const float* __restrict__ Wlv, const float* __restrict__ blv,
    const float* __restrict__ eps_z) {
  const int K = HQ;
  __shared__ float As[16][64];
  __shared__ float Ws[16][64];
  __shared__ float s_out[64][65];
  const int rb = blockIdx.x * 64;
  const int tid = threadIdx.x;
  const int tx = tid & 15, ty = tid >> 4;
  const int lm = tid >> 2;
  const int kq = (tid & 3) * 4;
  float acc[4][4] = {};
  for (int k0 = 0; k0 < K; k0 += 16) {
#pragma unroll
    for (int i = 0; i < 4; i++) {
      int k = k0 + kq + i;
      As[kq + i][lm] = (k < K) ? g_h[(size_t)(rb + lm) * K + k] : 0.f;
      float wv = 0.f;
      if (k < K)
        wv = (lm < 32) ? Wmu[(size_t)lm * K + k]
                       : Wlv[(size_t)(lm - 32) * K + k];
      Ws[kq + i][lm] = wv;
    }
    __syncthreads();
#pragma unroll
    for (int kk = 0; kk < 16; kk++) {
      float a[4], w[4];
#pragma unroll
      for (int i = 0; i < 4; i++) a[i] = As[kk][ty * 4 + i];
#pragma unroll
      for (int j = 0; j < 4; j++) w[j] = Ws[kk][tx * 4 + j];
#pragma unroll
      for (int i = 0; i < 4; i++)
#pragma unroll
        for (int j = 0; j < 4; j++) acc[i][j] += a[i] * w[j];
    }
    __syncthreads();
  }
#pragma unroll
  for (int i = 0; i < 4; i++)
#pragma unroll
    for (int j = 0; j < 4; j++) {
      int c = tx * 4 + j;
      float b = (c < 32) ? bmu[c] : blv[c - 32];
      s_out[ty * 4 + i][c] = fmaxf(acc[i][j] + b, 0.f);
    }
  __syncthreads();
  float kl = 0.f;
  for (int idx = tid; idx < 64 * 32; idx += 256) {
    int r = idx >> 5, c = idx & 31;
    float mu = s_out[r][c];
    float lv = s_out[r][c + 32];
    int row = rb + r;
    float elv = expf(lv);
    g_z[(size_t)row * LQ + c] =
        mu + eps_z[(size_t)row * LQ + c] * expf(0.5f * lv);
    kl += 0.5f * (mu * mu + elv - logf(1e-8f + elv) - 1.f);
  }
  __shared__ float sred[256];
  sred[tid] = kl;
  __syncthreads();
  for (int s = 128; s > 0; s >>= 1) {
    if (tid < s) sred[tid] += sred[tid + s];
    __syncthreads();
  }
  if (tid == 0) g_klpart[blockIdx.x] = sred[0];
}

// ---------------------------------------------------------------------------
// GEMM3 (SIMT): g_hd = rna(relu(z @ W_d1^T + b_d1))   K=32, N=392
// ---------------------------------------------------------------------------
__global__ __launch_bounds__(256) void k_gemm3(
    const float* __restrict__ W, const float* __restrict__ bias) {
  const int K = LQ, N = HQ;
  __shared__ float As[16][64];
  __shared__ float Ws[16][64];
  const int rb = blockIdx.x * 64;
  const int nb = blockIdx.y * 64;
  const int tid = threadIdx.x;
  const int tx = tid & 15, ty = tid >> 4;
  const int lm = tid >> 2;
  const int kq = (tid & 3) * 4;
  float acc[4][4] = {};
  for (int k0 = 0; k0 < K; k0 += 16) {
#pragma unroll
    for (int i = 0; i < 4; i++) {
      int k = k0 + kq + i;
      As[kq + i][lm] = g_z[(size_t)(rb + lm) * K + k];
      float wv = 0.f;
      int n = nb + lm;
      if (n < N) wv = W[(size_t)n * K + k];
      Ws[kq + i][lm] = wv;
    }
    __syncthreads();
#pragma unroll
    for (int kk = 0; kk < 16; kk++) {
      float a[4], w[4];
#pragma unroll
      for (int i = 0; i < 4; i++) a[i] = As[kk][ty * 4 + i];
#pragma unroll
      for (int j = 0; j < 4; j++) w[j] = Ws[kk][tx * 4 + j];
#pragma unroll
      for (int i = 0; i < 4; i++)
#pragma unroll
        for (int j = 0; j < 4; j++) acc[i][j] += a[i] * w[j];
    }
    __syncthreads();
  }
#pragma unroll
  for (int i = 0; i < 4; i++) {
    int r = rb + ty * 4 + i;
#pragma unroll
    for (int j = 0; j < 4; j++) {
      int n = nb + tx * 4 + j;
      if (n < N)
        g_hd[(size_t)r * N + n] = rna(fmaxf(acc[i][j] + bias[n], 0.f));
    }
  }
}

// ---------------------------------------------------------------------------
// Row reduction + final scalar
// ---------------------------------------------------------------------------
__global__ __launch_bounds__(256) void k_reduce_rows() {
  int row = blockIdx.x * 256 + threadIdx.x;
  float q = 0.f, l = 0.f;
#pragma unroll
  for (int t = 0; t < NT4; t++) {
    q += g_quadpart[(size_t)row * NT4 + t];
    l += g_ldpart[(size_t)row * NT4 + t];
  }
  float lp = -0.5f * (784.f * 1.8378770664093453f + l + q);
  __shared__ float sred[256];
  sred[threadIdx.x] = lp;
  __syncthreads();
  for (int s = 128; s > 0; s >>= 1) {
    if (threadIdx.x < s) sred[threadIdx.x] += sred[threadIdx.x + s];
    __syncthreads();
  }
  if (threadIdx.x == 0) g_lppart[blockIdx.x] = sred[0];
}

__global__ __launch_bounds__(256) void k_final(float* __restrict__ out,
                                               int out_size) {
  __shared__ double sd[256];
  int tid = threadIdx.x;
  sd[tid] = (double)g_lppart[tid];
  __syncthreads();
  for (int s = 128; s > 0; s >>= 1) {
    if (tid < s) sd[tid] += sd[tid + s];
    __syncthreads();
  }
  double lp_sum = sd[0];
  __syncthreads();
  double kl = 0.0;
  for (int i = tid; i < NB1; i += 256) kl += (double)g_klpart[i];
  sd[tid] = kl;
  __syncthreads();
  for (int s = 128; s > 0; s >>= 1) {
    if (tid < s) sd[tid] += sd[tid + s];
    __syncthreads();
  }
  if (tid == 0) {
    long long nimg = (long long)BQ * DQ;
    if ((long long)out_size > nimg)
      out[(size_t)nimg] = (float)(-(lp_sum) / (double)BQ + sd[0]);
  }
}

// ---------------------------------------------------------------------------
extern "C" void kernel_launch(void* const* d_in, const int* in_sizes, int n_in,
                              void* d_out, int out_size) {
  const float* x     = (const float*)d_in[0];
  const float* eps_z = (const float*)d_in[1];
  const float* eps_y = (const float*)d_in[2];
  const float* W_e1  = (const float*)d_in[3];
  const float* b_e1  = (const float*)d_in[4];
  const float* W_emu = (const float*)d_in[5];
  const float* b_emu = (const float*)d_in[6];
  const float* W_elv = (const float*)d_in[7];
  const float* b_elv = (const float*)d_in[8];
  const float* W_d1  = (const float*)d_in[9];
  const float* b_d1  = (const float*)d_in[10];
  const float* W_dmu = (const float*)d_in[11];
  const float* b_dmu = (const float*)d_in[12];
  const float* W_dlv = (const float*)d_in[13];
  const float* b_dlv = (const float*)d_in[14];
  float* out = (float*)d_out;

  cudaFuncSetAttribute(k1_mma, cudaFuncAttributeMaxDynamicSharedMemorySize,
                       K1_SMEM);
  cudaFuncSetAttribute(k4_mma, cudaFuncAttributeMaxDynamicSharedMemorySize,
                       K4_SMEM);

  float *d_xtf, *d_we1, *d_wdmu, *d_wdlv;
  cudaGetSymbolAddress((void**)&d_xtf, g_xtf);
  cudaGetSymbolAddress((void**)&d_we1, g_we1);
  cudaGetSymbolAddress((void**)&d_wdmu, g_wdmu);
  cudaGetSymbolAddress((void**)&d_wdlv, g_wdlv);

  const int NW4 = (HQ * DQ) / 4;  // 76832
  k_cvt<<<(NW4 + 255) / 256, 256>>>((const float4*)W_e1, (float4*)d_we1, NW4);
  k_cvt<<<(NW4 + 255) / 256, 256>>>((const float4*)W_dmu, (float4*)d_wdmu,
                                    NW4);
  k_cvt<<<(NW4 + 255) / 256, 256>>>((const float4*)W_dlv, (float4*)d_wdlv,
                                    NW4);
  const int NX4 = (int)(((size_t)BQ * DQ) / 4);
  k_cvt<<<4096, 256>>>((const float4*)x, (float4*)d_xtf, NX4);

  k1_mma<<<dim3(7, BQ / 128), 256, K1_SMEM>>>(d_xtf, d_we1, b_e1);
  k_gemm2<<<dim3(NB1, 1), 256>>>(W_emu, b_emu, W_elv, b_elv, eps_z);
  k_gemm3<<<dim3(NB1, 7), 256>>>(W_d1, b_d1);
  k4_mma<<<dim3(NT4, BQ / 128), 256, K4_SMEM>>>(d_wdmu, b_dmu, d_wdlv, b_dlv,
                                                x, eps_y, out);
  k_reduce_rows<<<NRED, 256>>>();
  k_final<<<1, 256>>>(out, out_size);
}

// round 7
// speedup vs baseline: 2.6225x; 1.0004x over previous
#include <cuda_runtime.h>
#include <math.h>
#include <stdint.h>

// Problem constants
#define BQ 65536
#define DQ 784
#define HQ 392
#define LQ 32
#define NT4 13                 // ceil(784/64) N-tiles in gemm4
#define NB1 ((BQ) / 64)        // row blocks for gemm2/3
#define NRED 256
#define SSTR 36                // smem row stride (floats), pad-4 conflict-free

// Scratch
__device__ float g_h[(size_t)BQ * HQ];
__device__ float g_z[(size_t)BQ * LQ];
__device__ float g_hd[(size_t)BQ * HQ];
__device__ float g_xtf[(size_t)BQ * DQ];     // rna(x) for k1 A operand
__device__ float g_we1[(size_t)HQ * DQ];     // rna(W_e1)
__device__ float g_wdmu[(size_t)DQ * HQ];    // rna(W_dmu)
__device__ float g_wdlv[(size_t)DQ * HQ];    // rna(W_dlv)
__device__ float g_quadpart[(size_t)BQ * NT4];
__device__ float g_ldpart[(size_t)BQ * NT4];
__device__ float g_klpart[NB1];
__device__ float g_lppart[NRED];

// ---------------------------------------------------------------------------
// helpers
// ---------------------------------------------------------------------------
__device__ __forceinline__ void cp16(uint32_t dst, const void* src,
                                     uint32_t sz) {
  asm volatile("cp.async.cg.shared.global [%0], [%1], 16, %2;"
               :: "r"(dst), "l"(__cvta_generic_to_global(src)), "r"(sz));
}
#define CP_COMMIT() asm volatile("cp.async.commit_group;" ::: "memory")
template <int N>
__device__ __forceinline__ void cp_wait() {
  asm volatile("cp.async.wait_group %0;" :: "n"(N) : "memory");
}
__device__ __forceinline__ uint32_t smem_u32(const void* p) {
  uint32_t a;
  asm("{ .reg .u64 t; cvta.to.shared.u64 t, %1; cvt.u32.u64 %0, t; }"
      : "=r"(a) : "l"(p));
  return a;
}
__device__ __forceinline__ float rna(float f) {
  uint32_t r;
  asm("cvt.rna.tf32.f32 %0, %1;" : "=r"(r) : "f"(f));
  return __uint_as_float(r);
}
// tf32 mma with raw fp32 bits (inputs pre-rounded with rna by producers)
__device__ __forceinline__ void mma8(float* d, const float* a, const float* b) {
  asm volatile(
      "mma.sync.aligned.m16n8k8.row.col.f32.tf32.tf32.f32 "
      "{%0,%1,%2,%3}, {%4,%5,%6,%7}, {%8,%9}, {%0,%1,%2,%3};"
      : "+f"(d[0]), "+f"(d[1]), "+f"(d[2]), "+f"(d[3])
      : "r"(__float_as_uint(a[0])), "r"(__float_as_uint(a[1])),
        "r"(__float_as_uint(a[2])), "r"(__float_as_uint(a[3])),
        "r"(__float_as_uint(b[0])), "r"(__float_as_uint(b[1])));
}

// ---------------------------------------------------------------------------
// rna pre-rounding copy (float4 grid-stride)
// ---------------------------------------------------------------------------
__global__ __launch_bounds__(256) void k_cvt(const float4* __restrict__ src,
                                             float4* __restrict__ dst,
                                             int n4) {
  int i = blockIdx.x * 256 + threadIdx.x;
  int stride = gridDim.x * 256;
  for (; i < n4; i += stride) {
    float4 v = src[i];
    v.x = rna(v.x);
    v.y = rna(v.y);
    v.z = rna(v.z);
    v.w = rna(v.w);
    dst[i] = v;
  }
}

// ---------------------------------------------------------------------------
// K1 (tf32 mma): g_h = relu(x @ W_e1^T + b_e1)   M=B, N=392, K=784
// Block tile 128x64, BK=32, 256 thr (8 warps 4Mx2N), 3-stage cp.async ring.
// ---------------------------------------------------------------------------
#define K1_NIT 25
__global__ __launch_bounds__(256, 2) void k1_mma(
    const float* __restrict__ A, const float* __restrict__ W,
    const float* __restrict__ bias) {
  extern __shared__ float sm[];
  const uint32_t sbase = smem_u32(sm);
  const int tid = threadIdx.x;
  const int lane = tid & 31, wid = tid >> 5;
  const int wm = wid & 3, wn = wid >> 2;
  const int qr = lane >> 2, qc = lane & 3;
  const int rb = blockIdx.y * 128;
  const int nb = blockIdx.x * 64;
  const int ar = tid >> 1, ac4 = (tid & 1) * 4;
  const int wr = tid >> 2, wc4 = (tid & 3) * 2;

  float acc[2][4][4] = {};

  auto stage = [&](int t) {
    const int s3 = t % 3;
    const int k0 = t * 32;
    const uint32_t abase = sbase + (uint32_t)(s3 * 4608) * 4u;
    const uint32_t wbase = sbase + (uint32_t)(13824 + s3 * 2304) * 4u;
    const float* gA = A + (size_t)(rb + ar) * DQ + k0;
#pragma unroll
    for (int i = 0; i < 4; i++) {
      int c4 = ac4 + i;
      uint32_t sz = (k0 + c4 * 4 < DQ) ? 16u : 0u;
      cp16(abase + (uint32_t)(ar * SSTR + c4 * 4) * 4u, gA + c4 * 4, sz);
    }
    const int n = nb + wr;
    const float* gW = W + (size_t)((n < HQ) ? n : 0) * DQ + k0;
#pragma unroll
    for (int i = 0; i < 2; i++) {
      int c4 = wc4 + i;
      uint32_t sz = ((n < HQ) && (k0 + c4 * 4 < DQ)) ? 16u : 0u;
      cp16(wbase + (uint32_t)(wr * SSTR + c4 * 4) * 4u, gW + c4 * 4, sz);
    }
  };

  stage(0);
  CP_COMMIT();
  stage(1);
  CP_COMMIT();
  for (int it = 0; it < K1_NIT; ++it) {
    if (it + 1 < K1_NIT) cp_wait<1>();
    else cp_wait<0>();
    __syncthreads();
    if (it + 2 < K1_NIT) {
      stage(it + 2);
      CP_COMMIT();
    }
    const int s3 = it % 3;
    const float* Ab = sm + s3 * 4608;
    const float* Wb = sm + 13824 + s3 * 2304;
#pragma unroll
    for (int kk = 0; kk < 4; kk++) {
      float af[2][4];
#pragma unroll
      for (int i = 0; i < 2; i++) {
        const float* p = Ab + (wm * 32 + i * 16 + qr) * SSTR + kk * 8 + qc;
        af[i][0] = p[0];
        af[i][1] = p[8 * SSTR];
        af[i][2] = p[4];
        af[i][3] = p[8 * SSTR + 4];
      }
      float bf[4][2];
#pragma unroll
      for (int j = 0; j < 4; j++) {
        const float* p = Wb + (wn * 32 + j * 8 + qr) * SSTR + kk * 8 + qc;
        bf[j][0] = p[0];
        bf[j][1] = p[4];
      }
#pragma unroll
      for (int i = 0; i < 2; i++)
#pragma unroll
        for (int j = 0; j < 4; j++) mma8(acc[i][j], af[i], bf[j]);
    }
  }
  // epilogue: relu + bias
#pragma unroll
  for (int i = 0; i < 2; i++) {
    int r0 = rb + wm * 32 + i * 16 + qr;
#pragma unroll
    for (int j = 0; j < 4; j++) {
      int col = nb + wn * 32 + j * 8 + qc * 2;
      if (col < HQ) {
        float b0 = bias[col], b1 = bias[col + 1];
        float2 v0 = make_float2(fmaxf(acc[i][j][0] + b0, 0.f),
                                fmaxf(acc[i][j][1] + b1, 0.f));
        float2 v1 = make_float2(fmaxf(acc[i][j][2] + b0, 0.f),
                                fmaxf(acc[i][j][3] + b1, 0.f));
        *(float2*)&g_h[(size_t)r0 * HQ + col] = v0;
        *(float2*)&g_h[(size_t)(r0 + 8) * HQ + col] = v1;
      }
    }
  }
}
#define K1_SMEM ((13824 + 3 * 2304) * 4)

// ---------------------------------------------------------------------------
// K4 (tf32 mma, dual): mu_y/lv_y from g_hd; fused sigmoid/out + partials.
// ---------------------------------------------------------------------------
#define K4_NIT 13
__global__ __launch_bounds__(256, 2) void k4_mma(
    const float* __restrict__ Wmu, const float* __restrict__ bmu,
    const float* __restrict__ Wlv, const float* __restrict__ blv,
    const float* __restrict__ x, const float* __restrict__ eps_y,
    float* __restrict__ out) {
  extern __shared__ float sm[];
  const uint32_t sbase = smem_u32(sm);
  const int tid = threadIdx.x;
  const int lane = tid & 31, wid = tid >> 5;
  const int wm = wid & 3, wn = wid >> 2;
  const int qr = lane >> 2, qc = lane & 3;
  const int rb = blockIdx.y * 128;
  const int nb = blockIdx.x * 64;
  const int ar = tid >> 1, ac4 = (tid & 1) * 4;
  const int wr = tid >> 2, wc4 = (tid & 3) * 2;

  float accM[2][4][4] = {};
  float accL[2][4][4] = {};

  auto stage = [&](int t) {
    const int s3 = t % 3;
    const int k0 = t * 32;
    const uint32_t abase = sbase + (uint32_t)(s3 * 4608) * 4u;
    const uint32_t mbase = sbase + (uint32_t)(13824 + s3 * 2304) * 4u;
    const uint32_t lbase = sbase + (uint32_t)(20736 + s3 * 2304) * 4u;
    const float* gA = g_hd + (size_t)(rb + ar) * HQ + k0;
#pragma unroll
    for (int i = 0; i < 4; i++) {
      int c4 = ac4 + i;
      uint32_t sz = (k0 + c4 * 4 < HQ) ? 16u : 0u;
      cp16(abase + (uint32_t)(ar * SSTR + c4 * 4) * 4u, gA + c4 * 4, sz);
    }
    const int n = nb + wr;
    const size_t wo = (size_t)((n < DQ) ? n : 0) * HQ + k0;
#pragma unroll
    for (int i = 0; i < 2; i++) {
      int c4 = wc4 + i;
      uint32_t sz = ((n < DQ) && (k0 + c4 * 4 < HQ)) ? 16u : 0u;
      uint32_t so = (uint32_t)(wr * SSTR + c4 * 4) * 4u;
      cp16(mbase + so, Wmu + wo + c4 * 4, sz);
      cp16(lbase + so, Wlv + wo + c4 * 4, sz);
    }
  };

  stage(0);
  CP_COMMIT();
  stage(1);
  CP_COMMIT();
  for (int it = 0; it < K4_NIT; ++it) {
    if (it + 1 < K4_NIT) cp_wait<1>();
    else cp_wait<0>();
    __syncthreads();
    if (it + 2 < K4_NIT) {
      stage(it + 2);
      CP_COMMIT();
    }
    const int s3 = it % 3;
    const float* Ab = sm + s3 * 4608;
    const float* Mb = sm + 13824 + s3 * 2304;
    const float* Lb = sm + 20736 + s3 * 2304;
#pragma unroll
    for (int kk = 0; kk < 4; kk++) {
      float af[2][4];
#pragma unroll
      for (int i = 0; i < 2; i++) {
        const float* p = Ab + (wm * 32 + i * 16 + qr) * SSTR + kk * 8 + qc;
        af[i][0] = p[0];
        af[i][1] = p[8 * SSTR];
        af[i][2] = p[4];
        af[i][3] = p[8 * SSTR + 4];
      }
      float bm[4][2], bl[4][2];
#pragma unroll
      for (int j = 0; j < 4; j++) {
        int o = (wn * 32 + j * 8 + qr) * SSTR + kk * 8 + qc;
        bm[j][0] = Mb[o];
        bm[j][1] = Mb[o + 4];
        bl[j][0] = Lb[o];
        bl[j][1] = Lb[o + 4];
      }
#pragma unroll
      for (int i = 0; i < 2; i++)
#pragma unroll
        for (int j = 0; j < 4; j++) {
          mma8(accM[i][j], af[i], bm[j]);
          mma8(accL[i][j], af[i], bl[j]);
        }
    }
  }

  // epilogue: sigmoid/out + deterministic row partials
  float* srq = sm + 27648;  // [128][2]
  float* srl = sm + 27904;  // [128][2]
  __syncthreads();
#pragma unroll
  for (int i = 0; i < 2; i++) {
#pragma unroll
    for (int half = 0; half < 2; half++) {
      const int rlocal = wm * 32 + i * 16 + qr + half * 8;
      const size_t row = rb + rlocal;
      float q = 0.f, l = 0.f;
#pragma unroll
      for (int j = 0; j < 4; j++) {
        int col = nb + wn * 32 + j * 8 + qc * 2;
#pragma unroll
        for (int e = 0; e < 2; e++) {
          int c = col + e;
          if (c < DQ) {
            float mu = fmaxf(accM[i][j][half * 2 + e] + bmu[c], 0.f);
            float lv = fmaxf(accL[i][j][half * 2 + e] + blv[c], 0.f);
            float s = __expf(0.5f * lv);
            size_t off = row * DQ + c;
            float t = mu + eps_y[off] * s;
            out[off] = __fdividef(1.f, 1.f + __expf(-t));
            float d = x[off] - mu;
            q += __fdividef(d * d, s);
            l += 0.5f * lv;
          }
        }
      }
      q += __shfl_xor_sync(0xffffffffu, q, 1);
      q += __shfl_xor_sync(0xffffffffu, q, 2);
      l += __shfl_xor_sync(0xffffffffu, l, 1);
      l += __shfl_xor_sync(0xffffffffu, l, 2);
      if (qc == 0) {
        srq[rlocal * 2 + wn] = q;
        srl[rlocal * 2 + wn] = l;
      }
    }
  }
  __syncthreads();
  if (tid < 128) {
    g_quadpart[(size_t)(rb + tid) * NT4 + blockIdx.x] =
        srq[tid * 2] + srq[tid * 2 + 1];
    g_ldpart[(size_t)(rb + tid) * NT4 + blockIdx.x] =
        srl[tid * 2] + srl[tid * 2 + 1];
  }
}
#define K4_SMEM (28160 * 4)

// ---------------------------------------------------------------------------
// GEMM2 (SIMT): mu_z/lv_z combined N=64, fused reparam + KL partial. K=392.
// ---------------------------------------------------------------------------
__global__ __launch_bounds__(256) void k_gemm2(
    const float* __restrict__ Wmu, const float* __restrict__ bmu,
    const float* __restrict__ Wlv, const float* __restrict__ blv,
    const float* __restrict__ eps_z) {
  const int K = HQ;
  __shared__ float As[16][64];
  __shared__ float Ws[16][64];
  __shared__ float s_out[64][65];
  const int rb = blockIdx.x * 64;
  const int tid = threadIdx.x;
  const int tx = tid & 15, ty = tid >> 4;
  const int lm = tid >> 2;
  const int kq = (tid & 3) * 4;
  float acc[4][4] = {};
  for (int k0 = 0; k0 < K; k0 += 16) {
#pragma unroll
    for (int i = 0; i < 4; i++) {
      int k = k0 + kq + i;
      As[kq + i][lm] = (k < K) ? g_h[(size_t)(rb + lm) * K + k] : 0.f;
      float wv = 0.f;
      if (k < K)
        wv = (lm < 32) ? Wmu[(size_t)lm * K + k]
                       : Wlv[(size_t)(lm - 32) * K + k];
      Ws[kq + i][lm] = wv;
    }
    __syncthreads();
#pragma unroll
    for (int kk = 0; kk < 16; kk++) {
      float a[4], w[4];
#pragma unroll
      for (int i = 0; i < 4; i++) a[i] = As[kk][ty * 4 + i];
#pragma unroll
      for (int j = 0; j < 4; j++) w[j] = Ws[kk][tx * 4 + j];
#pragma unroll
      for (int i = 0; i < 4; i++)
#pragma unroll
        for (int j = 0; j < 4; j++) acc[i][j] += a[i] * w[j];
    }
    __syncthreads();
  }
#pragma unroll
  for (int i = 0; i < 4; i++)
#pragma unroll
    for (int j = 0; j < 4; j++) {
      int c = tx * 4 + j;
      float b = (c < 32) ? bmu[c] : blv[c - 32];
      s_out[ty * 4 + i][c] = fmaxf(acc[i][j] + b, 0.f);
    }
  __syncthreads();
  float kl = 0.f;
  for (int idx = tid; idx < 64 * 32; idx += 256) {
    int r = idx >> 5, c = idx & 31;
    float mu = s_out[r][c];
    float lv = s_out[r][c + 32];
    int row = rb + r;
    float elv = expf(lv);
    g_z[(size_t)row * LQ + c] =
        mu + eps_z[(size_t)row * LQ + c] * expf(0.5f * lv);
    kl += 0.5f * (mu * mu + elv - logf(1e-8f + elv) - 1.f);
  }
  __shared__ float sred[256];
  sred[tid] = kl;
  __syncthreads();
  for (int s = 128; s > 0; s >>= 1) {
    if (tid < s) sred[tid] += sred[tid + s];
    __syncthreads();
  }
  if (tid == 0) g_klpart[blockIdx.x] = sred[0];
}

// ---------------------------------------------------------------------------
// GEMM3 (SIMT): g_hd = rna(relu(z @ W_d1^T + b_d1))   K=32, N=392
// ---------------------------------------------------------------------------
__global__ __launch_bounds__(256) void k_gemm3(
    const float* __restrict__ W, const float* __restrict__ bias) {
  const int K = LQ, N = HQ;
  __shared__ float As[16][64];
  __shared__ float Ws[16][64];
  const int rb = blockIdx.x * 64;
  const int nb = blockIdx.y * 64;
  const int tid = threadIdx.x;
  const int tx = tid & 15, ty = tid >> 4;
  const int lm = tid >> 2;
  const int kq = (tid & 3) * 4;
  float acc[4][4] = {};
  for (int k0 = 0; k0 < K; k0 += 16) {
#pragma unroll
    for (int i = 0; i < 4; i++) {
      int k = k0 + kq + i;
      As[kq + i][lm] = g_z[(size_t)(rb + lm) * K + k];
      float wv = 0.f;
      int n = nb + lm;
      if (n < N) wv = W[(size_t)n * K + k];
      Ws[kq + i][lm] = wv;
    }
    __syncthreads();
#pragma unroll
    for (int kk = 0; kk < 16; kk++) {
      float a[4], w[4];
#pragma unroll
      for (int i = 0; i < 4; i++) a[i] = As[kk][ty * 4 + i];
#pragma unroll
      for (int j = 0; j < 4; j++) w[j] = Ws[kk][tx * 4 + j];
#pragma unroll
      for (int i = 0; i < 4; i++)
#pragma unroll
        for (int j = 0; j < 4; j++) acc[i][j] += a[i] * w[j];
    }
    __syncthreads();
  }
#pragma unroll
  for (int i = 0; i < 4; i++) {
    int r = rb + ty * 4 + i;
#pragma unroll
    for (int j = 0; j < 4; j++) {
      int n = nb + tx * 4 + j;
      if (n < N)
        g_hd[(size_t)r * N + n] = rna(fmaxf(acc[i][j] + bias[n], 0.f));
    }
  }
}

// ---------------------------------------------------------------------------
// Row reduction + final scalar
// ---------------------------------------------------------------------------
__global__ __launch_bounds__(256) void k_reduce_rows() {
  int row = blockIdx.x * 256 + threadIdx.x;
  float q = 0.f, l = 0.f;
#pragma unroll
  for (int t = 0; t < NT4; t++) {
    q += g_quadpart[(size_t)row * NT4 + t];
    l += g_ldpart[(size_t)row * NT4 + t];
  }
  float lp = -0.5f * (784.f * 1.8378770664093453f + l + q);
  __shared__ float sred[256];
  sred[threadIdx.x] = lp;
  __syncthreads();
  for (int s = 128; s > 0; s >>= 1) {
    if (threadIdx.x < s) sred[threadIdx.x] += sred[threadIdx.x + s];
    __syncthreads();
  }
  if (threadIdx.x == 0) g_lppart[blockIdx.x] = sred[0];
}

__global__ __launch_bounds__(256) void k_final(float* __restrict__ out,
                                               int out_size) {
  __shared__ double sd[256];
  int tid = threadIdx.x;
  sd[tid] = (double)g_lppart[tid];
  __syncthreads();
  for (int s = 128; s > 0; s >>= 1) {
    if (tid < s) sd[tid] += sd[tid + s];
    __syncthreads();
  }
  double lp_sum = sd[0];
  __syncthreads();
  double kl = 0.0;
  for (int i = tid; i < NB1; i += 256) kl += (double)g_klpart[i];
  sd[tid] = kl;
  __syncthreads();
  for (int s = 128; s > 0; s >>= 1) {
    if (tid < s) sd[tid] += sd[tid + s];
    __syncthreads();
  }
  if (tid == 0) {
    long long nimg = (long long)BQ * DQ;
    if ((long long)out_size > nimg)
      out[(size_t)nimg] = (float)(-(lp_sum) / (double)BQ + sd[0]);
  }
}

// ---------------------------------------------------------------------------
extern "C" void kernel_launch(void* const* d_in, const int* in_sizes, int n_in,
                              void* d_out, int out_size) {
  const float* x     = (const float*)d_in[0];
  const float* eps_z = (const float*)d_in[1];
  const float* eps_y = (const float*)d_in[2];
  const float* W_e1  = (const float*)d_in[3];
  const float* b_e1  = (const float*)d_in[4];
  const float* W_emu = (const float*)d_in[5];
  const float* b_emu = (const float*)d_in[6];
  const float* W_elv = (const float*)d_in[7];
  const float* b_elv = (const float*)d_in[8];
  const float* W_d1  = (const float*)d_in[9];
  const float* b_d1  = (const float*)d_in[10];
  const float* W_dmu = (const float*)d_in[11];
  const float* b_dmu = (const float*)d_in[12];
  const float* W_dlv = (const float*)d_in[13];
  const float* b_dlv = (const float*)d_in[14];
  float* out = (float*)d_out;

  cudaFuncSetAttribute(k1_mma, cudaFuncAttributeMaxDynamicSharedMemorySize,
                       K1_SMEM);
  cudaFuncSetAttribute(k4_mma, cudaFuncAttributeMaxDynamicSharedMemorySize,
                       K4_SMEM);

  float *d_xtf, *d_we1, *d_wdmu, *d_wdlv;
  cudaGetSymbolAddress((void**)&d_xtf, g_xtf);
  cudaGetSymbolAddress((void**)&d_we1, g_we1);
  cudaGetSymbolAddress((void**)&d_wdmu, g_wdmu);
  cudaGetSymbolAddress((void**)&d_wdlv, g_wdlv);

  const int NW4 = (HQ * DQ) / 4;  // 76832
  k_cvt<<<(NW4 + 255) / 256, 256>>>((const float4*)W_e1, (float4*)d_we1, NW4);
  k_cvt<<<(NW4 + 255) / 256, 256>>>((const float4*)W_dmu, (float4*)d_wdmu,
                                    NW4);
  k_cvt<<<(NW4 + 255) / 256, 256>>>((const float4*)W_dlv, (float4*)d_wdlv,
                                    NW4);
  const int NX4 = (int)(((size_t)BQ * DQ) / 4);
  k_cvt<<<4096, 256>>>((const float4*)x, (float4*)d_xtf, NX4);

  k1_mma<<<dim3(7, BQ / 128), 256, K1_SMEM>>>(d_xtf, d_we1, b_e1);
  k_gemm2<<<dim3(NB1, 1), 256>>>(W_emu, b_emu, W_elv, b_elv, eps_z);
  k_gemm3<<<dim3(NB1, 7), 256>>>(W_d1, b_d1);
  k4_mma<<<dim3(NT4, BQ / 128), 256, K4_SMEM>>>(d_wdmu, b_dmu, d_wdlv, b_dlv,
                                                x, eps_y, out);
  k_reduce_rows<<<NRED, 256>>>();
  k_final<<<1, 256>>>(out, out_size);
}

// round 8
// speedup vs baseline: 2.8265x; 1.0778x over previous
#include <cuda_runtime.h>
#include <math.h>
#include <stdint.h>

// Problem constants
#define BQ 65536
#define DQ 784
#define HQ 392
#define LQ 32
#define NT4 13                 // ceil(784/64) N-tiles in gemm4
#define NB1 ((BQ) / 64)        // row blocks for gemm2/3
#define NRED 256
#define SSTR 36                // smem row stride (floats), pad-4 conflict-free

// Scratch
__device__ float g_h[(size_t)BQ * HQ];
__device__ float g_z[(size_t)BQ * LQ];
__device__ float g_hd[(size_t)BQ * HQ];
__device__ float g_we1[(size_t)HQ * DQ];     // rna(W_e1)
__device__ float g_wdmu[(size_t)DQ * HQ];    // rna(W_dmu)
__device__ float g_wdlv[(size_t)DQ * HQ];    // rna(W_dlv)
__device__ float g_quadpart[(size_t)BQ * NT4];
__device__ float g_ldpart[(size_t)BQ * NT4];
__device__ float g_klpart[NB1];
__device__ float g_lppart[NRED];

// ---------------------------------------------------------------------------
// helpers
// ---------------------------------------------------------------------------
__device__ __forceinline__ void cp16(uint32_t dst, const void* src,
                                     uint32_t sz) {
  asm volatile("cp.async.cg.shared.global [%0], [%1], 16, %2;"
               :: "r"(dst), "l"(__cvta_generic_to_global(src)), "r"(sz));
}
#define CP_COMMIT() asm volatile("cp.async.commit_group;" ::: "memory")
template <int N>
__device__ __forceinline__ void cp_wait() {
  asm volatile("cp.async.wait_group %0;" :: "n"(N) : "memory");
}
__device__ __forceinline__ uint32_t smem_u32(const void* p) {
  uint32_t a;
  asm("{ .reg .u64 t; cvta.to.shared.u64 t, %1; cvt.u32.u64 %0, t; }"
      : "=r"(a) : "l"(p));
  return a;
}
__device__ __forceinline__ float rna(float f) {
  uint32_t r;
  asm("cvt.rna.tf32.f32 %0, %1;" : "=r"(r) : "f"(f));
  return __uint_as_float(r);
}
__device__ __forceinline__ uint32_t rna_u(uint32_t f) {
  uint32_t r;
  asm("cvt.rna.tf32.f32 %0, %1;" : "=r"(r) : "f"(__uint_as_float(f)));
  return r;
}
// ldmatrix x4: tf32 fragments via b16 view (8x4 f32 block == 8x8 b16 matrix)
__device__ __forceinline__ void ldsm4(uint32_t* r, uint32_t addr) {
  asm volatile(
      "ldmatrix.sync.aligned.m8n8.x4.shared.b16 {%0,%1,%2,%3}, [%4];"
      : "=r"(r[0]), "=r"(r[1]), "=r"(r[2]), "=r"(r[3]) : "r"(addr));
}
// tf32 mma, raw register bits (inputs pre-rounded with rna by producers)
__device__ __forceinline__ void mma8u(float* d, const uint32_t* a,
                                      const uint32_t* b) {
  asm volatile(
      "mma.sync.aligned.m16n8k8.row.col.f32.tf32.tf32.f32 "
      "{%0,%1,%2,%3}, {%4,%5,%6,%7}, {%8,%9}, {%0,%1,%2,%3};"
      : "+f"(d[0]), "+f"(d[1]), "+f"(d[2]), "+f"(d[3])
      : "r"(a[0]), "r"(a[1]), "r"(a[2]), "r"(a[3]), "r"(b[0]), "r"(b[1]));
}

// ---------------------------------------------------------------------------
// rna pre-rounding copy (float4 grid-stride) — weights only (small)
// ---------------------------------------------------------------------------
__global__ __launch_bounds__(256) void k_cvt(const float4* __restrict__ src,
                                             float4* __restrict__ dst,
                                             int n4) {
  int i = blockIdx.x * 256 + threadIdx.x;
  int stride = gridDim.x * 256;
  for (; i < n4; i += stride) {
    float4 v = src[i];
    v.x = rna(v.x);
    v.y = rna(v.y);
    v.z = rna(v.z);
    v.w = rna(v.w);
    dst[i] = v;
  }
}

// ---------------------------------------------------------------------------
// K1 (tf32 mma + ldmatrix): g_h = relu(x @ W_e1^T + b_e1)  M=B, N=392, K=784
// Block tile 128x64, BK=32, 256 thr (8 warps 4Mx2N), 3-stage cp.async ring.
// A fragments rna-rounded in-register (x is raw fp32 input).
// ---------------------------------------------------------------------------
#define K1_NIT 25
__global__ __launch_bounds__(256, 2) void k1_mma(
    const float* __restrict__ A, const float* __restrict__ W,
    const float* __restrict__ bias) {
  extern __shared__ float sm[];
  const uint32_t sbase = smem_u32(sm);
  const int tid = threadIdx.x;
  const int lane = tid & 31, wid = tid >> 5;
  const int wm = wid & 3, wn = wid >> 2;
  const int qr = lane >> 2, qc = lane & 3;
  const int rb = blockIdx.y * 128;
  const int nb = blockIdx.x * 64;
  const int ar = tid >> 1, ac4 = (tid & 1) * 4;
  const int wr = tid >> 2, wc4 = (tid & 3) * 2;

  // ldmatrix per-thread offsets (bytes)
  uint32_t aoff[2], boff[2];
#pragma unroll
  for (int i = 0; i < 2; i++)
    aoff[i] = (uint32_t)((wm * 32 + i * 16 + (lane & 15)) * SSTR) * 4u +
              (uint32_t)((lane >> 4) & 1) * 16u;
#pragma unroll
  for (int p = 0; p < 2; p++)
    boff[p] = (uint32_t)((wn * 32 + (2 * p + ((lane >> 4) & 1)) * 8 +
                          (lane & 7)) * SSTR) * 4u +
              (uint32_t)((lane >> 3) & 1) * 16u;

  float acc[2][4][4] = {};

  auto stage = [&](int t) {
    const int s3 = t % 3;
    const int k0 = t * 32;
    const uint32_t abase = sbase + (uint32_t)(s3 * 4608) * 4u;
    const uint32_t wbase = sbase + (uint32_t)(13824 + s3 * 2304) * 4u;
    const float* gA = A + (size_t)(rb + ar) * DQ + k0;
#pragma unroll
    for (int i = 0; i < 4; i++) {
      int c4 = ac4 + i;
      uint32_t sz = (k0 + c4 * 4 < DQ) ? 16u : 0u;
      cp16(abase + (uint32_t)(ar * SSTR + c4 * 4) * 4u, gA + c4 * 4, sz);
    }
    const int n = nb + wr;
    const float* gW = W + (size_t)((n < HQ) ? n : 0) * DQ + k0;
#pragma unroll
    for (int i = 0; i < 2; i++) {
      int c4 = wc4 + i;
      uint32_t sz = ((n < HQ) && (k0 + c4 * 4 < DQ)) ? 16u : 0u;
      cp16(wbase + (uint32_t)(wr * SSTR + c4 * 4) * 4u, gW + c4 * 4, sz);
    }
  };

  stage(0);
  CP_COMMIT();
  stage(1);
  CP_COMMIT();
  for (int it = 0; it < K1_NIT; ++it) {
    if (it + 1 < K1_NIT) cp_wait<1>();
    else cp_wait<0>();
    __syncthreads();
    if (it + 2 < K1_NIT) {
      stage(it + 2);
      CP_COMMIT();
    }
    const int s3 = it % 3;
    const uint32_t abase = sbase + (uint32_t)(s3 * 4608) * 4u;
    const uint32_t wbase = sbase + (uint32_t)(13824 + s3 * 2304) * 4u;
#pragma unroll
    for (int kk = 0; kk < 4; kk++) {
      uint32_t af[2][4], bf[2][4];
#pragma unroll
      for (int i = 0; i < 2; i++) ldsm4(af[i], abase + aoff[i] + kk * 32);
#pragma unroll
      for (int p = 0; p < 2; p++) ldsm4(bf[p], wbase + boff[p] + kk * 32);
      // rna-round A fragments (x is raw fp32)
#pragma unroll
      for (int i = 0; i < 2; i++)
#pragma unroll
        for (int t = 0; t < 4; t++) af[i][t] = rna_u(af[i][t]);
#pragma unroll
      for (int i = 0; i < 2; i++) {
        mma8u(acc[i][0], af[i], &bf[0][0]);
        mma8u(acc[i][1], af[i], &bf[0][2]);
        mma8u(acc[i][2], af[i], &bf[1][0]);
        mma8u(acc[i][3], af[i], &bf[1][2]);
      }
    }
  }
  // epilogue: relu + bias
#pragma unroll
  for (int i = 0; i < 2; i++) {
    int r0 = rb + wm * 32 + i * 16 + qr;
#pragma unroll
    for (int j = 0; j < 4; j++) {
      int col = nb + wn * 32 + j * 8 + qc * 2;
      if (col < HQ) {
        float b0 = bias[col], b1 = bias[col + 1];
        float2 v0 = make_float2(fmaxf(acc[i][j][0] + b0, 0.f),
                                fmaxf(acc[i][j][1] + b1, 0.f));
        float2 v1 = make_float2(fmaxf(acc[i][j][2] + b0, 0.f),
                                fmaxf(acc[i][j][3] + b1, 0.f));
        *(float2*)&g_h[(size_t)r0 * HQ + col] = v0;
        *(float2*)&g_h[(size_t)(r0 + 8) * HQ + col] = v1;
      }
    }
  }
}
#define K1_SMEM ((13824 + 3 * 2304) * 4)

// ---------------------------------------------------------------------------
// K4 (tf32 mma + ldmatrix, dual): mu_y/lv_y from g_hd; fused epilogue.
// ---------------------------------------------------------------------------
#define K4_NIT 13
__global__ __launch_bounds__(256, 2) void k4_mma(
    const float* __restrict__ Wmu, const float* __restrict__ bmu,
    const float* __restrict__ Wlv, const float* __restrict__ blv,
    const float* __restrict__ x, const float* __restrict__ eps_y,
    float* __restrict__ out) {
  extern __shared__ float sm[];
  const uint32_t sbase = smem_u32(sm);
  const int tid = threadIdx.x;
  const int lane = tid & 31, wid = tid >> 5;
  const int wm = wid & 3, wn = wid >> 2;
  const int qr = lane >> 2, qc = lane & 3;
  const int rb = blockIdx.y * 128;
  const int nb = blockIdx.x * 64;
  const int ar = tid >> 1, ac4 = (tid & 1) * 4;
  const int wr = tid >> 2, wc4 = (tid & 3) * 2;

  uint32_t aoff[2], boff[2];
#pragma unroll
  for (int i = 0; i < 2; i++)
    aoff[i] = (uint32_t)((wm * 32 + i * 16 + (lane & 15)) * SSTR) * 4u +
              (uint32_t)((lane >> 4) & 1) * 16u;
#pragma unroll
  for (int p = 0; p < 2; p++)
    boff[p] = (uint32_t)((wn * 32 + (2 * p + ((lane >> 4) & 1)) * 8 +
                          (lane & 7)) * SSTR) * 4u +
              (uint32_t)((lane >> 3) & 1) * 16u;

  float accM[2][4][4] = {};
  float accL[2][4][4] = {};

  auto stage = [&](int t) {
    const int s3 = t % 3;
    const int k0 = t * 32;
    const uint32_t abase = sbase + (uint32_t)(s3 * 4608) * 4u;
    const uint32_t mbase = sbase + (uint32_t)(13824 + s3 * 2304) * 4u;
    const uint32_t lbase = sbase + (uint32_t)(20736 + s3 * 2304) * 4u;
    const float* gA = g_hd + (size_t)(rb + ar) * HQ + k0;
#pragma unroll
    for (int i = 0; i < 4; i++) {
      int c4 = ac4 + i;
      uint32_t sz = (k0 + c4 * 4 < HQ) ? 16u : 0u;
      cp16(abase + (uint32_t)(ar * SSTR + c4 * 4) * 4u, gA + c4 * 4, sz);
    }
    const int n = nb + wr;
    const size_t wo = (size_t)((n < DQ) ? n : 0) * HQ + k0;
#pragma unroll
    for (int i = 0; i < 2; i++) {
      int c4 = wc4 + i;
      uint32_t sz = ((n < DQ) && (k0 + c4 * 4 < HQ)) ? 16u : 0u;
      uint32_t so = (uint32_t)(wr * SSTR + c4 * 4) * 4u;
      cp16(mbase + so, Wmu + wo + c4 * 4, sz);
      cp16(lbase + so, Wlv + wo + c4 * 4, sz);
    }
  };

  stage(0);
  CP_COMMIT();
  stage(1);
  CP_COMMIT();
  for (int it = 0; it < K4_NIT; ++it) {
    if (it + 1 < K4_NIT) cp_wait<1>();
    else cp_wait<0>();
    __syncthreads();
    if (it + 2 < K4_NIT) {
      stage(it + 2);
      CP_COMMIT();
    }
    const int s3 = it % 3;
    const uint32_t abase = sbase + (uint32_t)(s3 * 4608) * 4u;
    const uint32_t mbase = sbase + (uint32_t)(13824 + s3 * 2304) * 4u;
    const uint32_t lbase = sbase + (uint32_t)(20736 + s3 * 2304) * 4u;
#pragma unroll
    for (int kk = 0; kk < 4; kk++) {
      uint32_t af[2][4], bm[2][4], bl[2][4];
#pragma unroll
      for (int i = 0; i < 2; i++) ldsm4(af[i], abase + aoff[i] + kk * 32);
#pragma unroll
      for (int p = 0; p < 2; p++) {
        ldsm4(bm[p], mbase + boff[p] + kk * 32);
        ldsm4(bl[p], lbase + boff[p] + kk * 32);
      }
#pragma unroll
      for (int i = 0; i < 2; i++) {
        mma8u(accM[i][0], af[i], &bm[0][0]);
        mma8u(accM[i][1], af[i], &bm[0][2]);
        mma8u(accM[i][2], af[i], &bm[1][0]);
        mma8u(accM[i][3], af[i], &bm[1][2]);
        mma8u(accL[i][0], af[i], &bl[0][0]);
        mma8u(accL[i][1], af[i], &bl[0][2]);
        mma8u(accL[i][2], af[i], &bl[1][0]);
        mma8u(accL[i][3], af[i], &bl[1][2]);
      }
    }
  }

  // epilogue: sigmoid/out + deterministic row partials
  float* srq = sm + 27648;  // [128][2]
  float* srl = sm + 27904;  // [128][2]
  __syncthreads();
#pragma unroll
  for (int i = 0; i < 2; i++) {
#pragma unroll
    for (int half = 0; half < 2; half++) {
      const int rlocal = wm * 32 + i * 16 + qr + half * 8;
      const size_t row = rb + rlocal;
      float q = 0.f, l = 0.f;
#pragma unroll
      for (int j = 0; j < 4; j++) {
        int col = nb + wn * 32 + j * 8 + qc * 2;
#pragma unroll
        for (int e = 0; e < 2; e++) {
          int c = col + e;
          if (c < DQ) {
            float mu = fmaxf(accM[i][j][half * 2 + e] + bmu[c], 0.f);
            float lv = fmaxf(accL[i][j][half * 2 + e] + blv[c], 0.f);
            float s = __expf(0.5f * lv);
            size_t off = row * DQ + c;
            float t = mu + eps_y[off] * s;
            out[off] = __fdividef(1.f, 1.f + __expf(-t));
            float d = x[off] - mu;
            q += __fdividef(d * d, s);
            l += 0.5f * lv;
          }
        }
      }
      q += __shfl_xor_sync(0xffffffffu, q, 1);
      q += __shfl_xor_sync(0xffffffffu, q, 2);
      l += __shfl_xor_sync(0xffffffffu, l, 1);
      l += __shfl_xor_sync(0xffffffffu, l, 2);
      if (qc == 0) {
        srq[rlocal * 2 + wn] = q;
        srl[rlocal * 2 + wn] = l;
      }
    }
  }
  __syncthreads();
  if (tid < 128) {
    g_quadpart[(size_t)(rb + tid) * NT4 + blockIdx.x] =
        srq[tid * 2] + srq[tid * 2 + 1];
    g_ldpart[(size_t)(rb + tid) * NT4 + blockIdx.x] =
        srl[tid * 2] + srl[tid * 2 + 1];
  }
}
#define K4_SMEM (28160 * 4)

// ---------------------------------------------------------------------------
// GEMM2 (SIMT): mu_z/lv_z combined N=64, fused reparam + KL partial. K=392.
// ---------------------------------------------------------------------------
__global__ __launch_bounds__(256) void k_gemm2(
    const float* __restrict__ Wmu, const float* __restrict__ bmu,
    const float* __restrict__ Wlv, const float* __restrict__ blv,
    const float* __restrict__ eps_z) {
  const int K = HQ;
  __shared__ float As[16][64];
  __shared__ float Ws[16][64];
  __shared__ float s_out[64][65];
  const int rb = blockIdx.x * 64;
  const int tid = threadIdx.x;
  const int tx = tid & 15, ty = tid >> 4;
  const int lm = tid >> 2;
  const int kq = (tid & 3) * 4;
  float acc[4][4] = {};
  for (int k0 = 0; k0 < K; k0 += 16) {
#pragma unroll
    for (int i = 0; i < 4; i++) {
      int k = k0 + kq + i;
      As[kq + i][lm] = (k < K) ? g_h[(size_t)(rb + lm) * K + k] : 0.f;
      float wv = 0.f;
      if (k < K)
        wv = (lm < 32) ? Wmu[(size_t)lm * K + k]
                       : Wlv[(size_t)(lm - 32) * K + k];
      Ws[kq + i][lm] = wv;
    }
    __syncthreads();
#pragma unroll
    for (int kk = 0; kk < 16; kk++) {
      float a[4], w[4];
#pragma unroll
      for (int i = 0; i < 4; i++) a[i] = As[kk][ty * 4 + i];
#pragma unroll
      for (int j = 0; j < 4; j++) w[j] = Ws[kk][tx * 4 + j];
#pragma unroll
      for (int i = 0; i < 4; i++)
#pragma unroll
        for (int j = 0; j < 4; j++) acc[i][j] += a[i] * w[j];
    }
    __syncthreads();
  }
#pragma unroll
  for (int i = 0; i < 4; i++)
#pragma unroll
    for (int j = 0; j < 4; j++) {
      int c = tx * 4 + j;
      float b = (c < 32) ? bmu[c] : blv[c - 32];
      s_out[ty * 4 + i][c] = fmaxf(acc[i][j] + b, 0.f);
    }
  __syncthreads();
  float kl = 0.f;
  for (int idx = tid; idx < 64 * 32; idx += 256) {
    int r = idx >> 5, c = idx & 31;
    float mu = s_out[r][c];
    float lv = s_out[r][c + 32];
    int row = rb + r;
    float elv = expf(lv);
    g_z[(size_t)row * LQ + c] =
        mu + eps_z[(size_t)row * LQ + c] * expf(0.5f * lv);
    kl += 0.5f * (mu * mu + elv - logf(1e-8f + elv) - 1.f);
  }
  __shared__ float sred[256];
  sred[tid] = kl;
  __syncthreads();
  for (int s = 128; s > 0; s >>= 1) {
    if (tid < s) sred[tid] += sred[tid + s];
    __syncthreads();
  }
  if (tid == 0) g_klpart[blockIdx.x] = sred[0];
}

// ---------------------------------------------------------------------------
// GEMM3 (SIMT): g_hd = rna(relu(z @ W_d1^T + b_d1))   K=32, N=392
// ---------------------------------------------------------------------------
__global__ __launch_bounds__(256) void k_gemm3(
    const float* __restrict__ W, const float* __restrict__ bias) {
  const int K = LQ, N = HQ;
  __shared__ float As[16][64];
  __shared__ float Ws[16][64];
  const int rb = blockIdx.x * 64;
  const int nb = blockIdx.y * 64;
  const int tid = threadIdx.x;
  const int tx = tid & 15, ty = tid >> 4;
  const int lm = tid >> 2;
  const int kq = (tid & 3) * 4;
  float acc[4][4] = {};
  for (int k0 = 0; k0 < K; k0 += 16) {
#pragma unroll
    for (int i = 0; i < 4; i++) {
      int k = k0 + kq + i;
      As[kq + i][lm] = g_z[(size_t)(rb + lm) * K + k];
      float wv = 0.f;
      int n = nb + lm;
      if (n < N) wv = W[(size_t)n * K + k];
      Ws[kq + i][lm] = wv;
    }
    __syncthreads();
#pragma unroll
    for (int kk = 0; kk < 16; kk++) {
      float a[4], w[4];
#pragma unroll
      for (int i = 0; i < 4; i++) a[i] = As[kk][ty * 4 + i];
#pragma unroll
      for (int j = 0; j < 4; j++) w[j] = Ws[kk][tx * 4 + j];
#pragma unroll
      for (int i = 0; i < 4; i++)
#pragma unroll
        for (int j = 0; j < 4; j++) acc[i][j] += a[i] * w[j];
    }
    __syncthreads();
  }
#pragma unroll
  for (int i = 0; i < 4; i++) {
    int r = rb + ty * 4 + i;
#pragma unroll
    for (int j = 0; j < 4; j++) {
      int n = nb + tx * 4 + j;
      if (n < N)
        g_hd[(size_t)r * N + n] = rna(fmaxf(acc[i][j] + bias[n], 0.f));
    }
  }
}

// ---------------------------------------------------------------------------
// Row reduction + final scalar
// ---------------------------------------------------------------------------
__global__ __launch_bounds__(256) void k_reduce_rows() {
  int row = blockIdx.x * 256 + threadIdx.x;
  float q = 0.f, l = 0.f;
#pragma unroll
  for (int t = 0; t < NT4; t++) {
    q += g_quadpart[(size_t)row * NT4 + t];
    l += g_ldpart[(size_t)row * NT4 + t];
  }
  float lp = -0.5f * (784.f * 1.8378770664093453f + l + q);
  __shared__ float sred[256];
  sred[threadIdx.x] = lp;
  __syncthreads();
  for (int s = 128; s > 0; s >>= 1) {
    if (threadIdx.x < s) sred[threadIdx.x] += sred[threadIdx.x + s];
    __syncthreads();
  }
  if (threadIdx.x == 0) g_lppart[blockIdx.x] = sred[0];
}

__global__ __launch_bounds__(256) void k_final(float* __restrict__ out,
                                               int out_size) {
  __shared__ double sd[256];
  int tid = threadIdx.x;
  sd[tid] = (double)g_lppart[tid];
  __syncthreads();
  for (int s = 128; s > 0; s >>= 1) {
    if (tid < s) sd[tid] += sd[tid + s];
    __syncthreads();
  }
  double lp_sum = sd[0];
  __syncthreads();
  double kl = 0.0;
  for (int i = tid; i < NB1; i += 256) kl += (double)g_klpart[i];
  sd[tid] = kl;
  __syncthreads();
  for (int s = 128; s > 0; s >>= 1) {
    if (tid < s) sd[tid] += sd[tid + s];
    __syncthreads();
  }
  if (tid == 0) {
    long long nimg = (long long)BQ * DQ;
    if ((long long)out_size > nimg)
      out[(size_t)nimg] = (float)(-(lp_sum) / (double)BQ + sd[0]);
  }
}

// ---------------------------------------------------------------------------
extern "C" void kernel_launch(void* const* d_in, const int* in_sizes, int n_in,
                              void* d_out, int out_size) {
  const float* x     = (const float*)d_in[0];
  const float* eps_z = (const float*)d_in[1];
  const float* eps_y = (const float*)d_in[2];
  const float* W_e1  = (const float*)d_in[3];
  const float* b_e1  = (const float*)d_in[4];
  const float* W_emu = (const float*)d_in[5];
  const float* b_emu = (const float*)d_in[6];
  const float* W_elv = (const float*)d_in[7];
  const float* b_elv = (const float*)d_in[8];
  const float* W_d1  = (const float*)d_in[9];
  const float* b_d1  = (const float*)d_in[10];
  const float* W_dmu = (const float*)d_in[11];
  const float* b_dmu = (const float*)d_in[12];
  const float* W_dlv = (const float*)d_in[13];
  const float* b_dlv = (const float*)d_in[14];
  float* out = (float*)d_out;

  cudaFuncSetAttribute(k1_mma, cudaFuncAttributeMaxDynamicSharedMemorySize,
                       K1_SMEM);
  cudaFuncSetAttribute(k4_mma, cudaFuncAttributeMaxDynamicSharedMemorySize,
                       K4_SMEM);

  float *d_we1, *d_wdmu, *d_wdlv;
  cudaGetSymbolAddress((void**)&d_we1, g_we1);
  cudaGetSymbolAddress((void**)&d_wdmu, g_wdmu);
  cudaGetSymbolAddress((void**)&d_wdlv, g_wdlv);

  const int NW4 = (HQ * DQ) / 4;  // 76832
  k_cvt<<<(NW4 + 255) / 256, 256>>>((const float4*)W_e1, (float4*)d_we1, NW4);
  k_cvt<<<(NW4 + 255) / 256, 256>>>((const float4*)W_dmu, (float4*)d_wdmu,
                                    NW4);
  k_cvt<<<(NW4 + 255) / 256, 256>>>((const float4*)W_dlv, (float4*)d_wdlv,
                                    NW4);

  k1_mma<<<dim3(7, BQ / 128), 256, K1_SMEM>>>(x, d_we1, b_e1);
  k_gemm2<<<dim3(NB1, 1), 256>>>(W_emu, b_emu, W_elv, b_elv, eps_z);
  k_gemm3<<<dim3(NB1, 7), 256>>>(W_d1, b_d1);
  k4_mma<<<dim3(NT4, BQ / 128), 256, K4_SMEM>>>(d_wdmu, b_dmu, d_wdlv, b_dlv,
                                                x, eps_y, out);
  k_reduce_rows<<<NRED, 256>>>();
  k_final<<<1, 256>>>(out, out_size);
}